// round 10
// baseline (speedup 1.0000x reference)
#include <cuda_runtime.h>
#include <cstdint>

// Problem constants
#define B_   32
#define C_   192
#define H_   64
#define W_   64
#define OH_  32
#define OW_  32

// -------- device scratch (no mallocs allowed) --------
__device__ float g_psum[16][C_];
__device__ float g_pss[16][C_];
__device__ unsigned g_wbf[2 * 9 * C_ * (C_ / 2)];         // bf16x2 weights [br][tap][oc][ic/2]
__device__ unsigned g_abits[2][6][B_][H_][2][32];         // bits [br][plane][b][y][par][j]
__device__ float    g_sc[B_][C_][OH_][OW_];               // shared avgpool shortcut

// ---------------- PTX helpers (sm_80-compatible) ----------------
__device__ __forceinline__ uint32_t smem_to_u32(const void* p) {
    uint32_t a;
    asm("{ .reg .u64 t; cvta.to.shared.u64 t, %1; cvt.u32.u64 %0, t; }" : "=r"(a) : "l"(p));
    return a;
}
#define CP_ASYNC16(dst, src, sz) \
    asm volatile("cp.async.cg.shared.global [%0], [%1], 16, %2;" \
        :: "r"(dst), "l"(src), "r"(sz) : "memory")
#define CP_COMMIT() asm volatile("cp.async.commit_group;" ::: "memory")
#define CP_WAIT0()  asm volatile("cp.async.wait_group 0;" ::: "memory")
#define LDSM_X4(r, addr) \
    asm volatile("ldmatrix.sync.aligned.m8n8.x4.shared.b16 {%0,%1,%2,%3}, [%4];" \
        : "=r"((r)[0]), "=r"((r)[1]), "=r"((r)[2]), "=r"((r)[3]) : "r"(addr))
#define MMA16816(d, a, b0, b1) \
    asm volatile("mma.sync.aligned.m16n8k16.row.col.f32.bf16.bf16.f32 " \
        "{%0,%1,%2,%3}, {%4,%5,%6,%7}, {%8,%9}, {%0,%1,%2,%3};" \
        : "+f"((d)[0]), "+f"((d)[1]), "+f"((d)[2]), "+f"((d)[3]) \
        : "r"((a)[0]), "r"((a)[1]), "r"((a)[2]), "r"((a)[3]), "r"(b0), "r"(b1))

// ================= K1: per-channel partial sums (16-way) =================
__global__ void k_stats(const float* __restrict__ x) {
    int c = blockIdx.x;
    int s = blockIdx.y;
    int tid = threadIdx.x;
    float sm = 0.f, ss = 0.f;
    for (int b = 2 * s; b < 2 * s + 2; b++) {
        const float4* p = (const float4*)(x + ((size_t)(b * C_ + c)) * (H_ * W_));
#pragma unroll
        for (int i = tid; i < (H_ * W_) / 4; i += 256) {
            float4 v = p[i];
            sm += (v.x + v.y) + (v.z + v.w);
            ss += fmaf(v.x, v.x, v.y * v.y) + fmaf(v.z, v.z, v.w * v.w);
        }
    }
    __shared__ float sh1[256], sh2[256];
    sh1[tid] = sm; sh2[tid] = ss;
    __syncthreads();
    for (int st = 128; st > 0; st >>= 1) {
        if (tid < st) { sh1[tid] += sh1[tid + st]; sh2[tid] += sh2[tid + st]; }
        __syncthreads();
    }
    if (tid == 0) { g_psum[s][c] = sh1[0]; g_pss[s][c] = sh2[0]; }
}

// ================= K2: pack weights to bf16 +-1, [br][tap][oc][ic] =========
__global__ void k_wpack(const float* __restrict__ w1, const float* __restrict__ w2) {
    int i = blockIdx.x * 256 + threadIdx.x;
    if (i >= 2 * 9 * C_ * (C_ / 2)) return;
    int cw = i % (C_ / 2);
    int t = i / (C_ / 2);
    int oc = t % C_; t /= C_;
    int tap = t % 9;
    int br = t / 9;
    int ky = tap / 3, kx = tap % 3;
    const float* w = br ? w2 : w1;
    int c0 = 2 * cw;
    float v0 = w[((oc * C_ + c0) * 3 + ky) * 3 + kx];
    float v1 = w[((oc * C_ + c0 + 1) * 3 + ky) * 3 + kx];
    unsigned lo = v0 > 0.f ? 0x3F80u : 0xBF80u;
    unsigned hi = v1 > 0.f ? 0x3F80u : 0xBF80u;
    g_wbf[i] = lo | (hi << 16);
}

// ========== K3: fused stats-finalize + binarize (plane layout) + avgpool ==========
__global__ void __launch_bounds__(256) k_pack(const float* __restrict__ x,
                                              const float* __restrict__ g1,
                                              const float* __restrict__ b1,
                                              const float* __restrict__ g2,
                                              const float* __restrict__ b2) {
    __shared__ float s_scale[2 * C_], s_shift[2 * C_];
    int tid = threadIdx.x;
    for (int i = tid; i < 2 * C_; i += 256) {
        int br = i / C_, c = i % C_;
        float s = 0.f, q = 0.f;
#pragma unroll
        for (int k = 0; k < 16; k++) { s += g_psum[k][c]; q += g_pss[k][c]; }
        const float invn = 1.f / (float)(B_ * H_ * W_);
        float mu = s * invn;
        float var = q * invn - mu * mu;
        float rstd = rsqrtf(var + 1e-5f);
        float gamma = br ? g2[c] : g1[c];
        float beta  = br ? b2[c] : b1[c];
        float sc = gamma * rstd;
        s_scale[i] = sc;
        s_shift[i] = beta - sc * mu;
    }
    __syncthreads();

    int gw = blockIdx.x * 8 + (tid >> 5);
    int lane = tid & 31;
    int b = gw / (OH_ * 6);
    int rem = gw % (OH_ * 6);
    int oy = rem / 6;
    int wp = rem % 6;
    int c0 = wp * 32;

    const float* px = x + ((size_t)(b * C_ + c0)) * (H_ * W_) + (2 * oy) * W_ + 2 * lane;
    float* psc = &g_sc[b][c0][oy][lane];
    int y0 = 2 * oy;

    unsigned acc[8];
#pragma unroll
    for (int k = 0; k < 8; k++) acc[k] = 0;

#pragma unroll 8
    for (int j = 0; j < 32; j++) {
        int c = c0 + j;
        const float* pc = px + (size_t)j * (H_ * W_);
        float2 r0 = *(const float2*)pc;
        float2 r1 = *(const float2*)(pc + W_);
        psc[(size_t)j * (OH_ * OW_)] = (r0.x + r0.y + r1.x + r1.y) * 0.25f;
        float s0 = s_scale[c],      t0 = s_shift[c];
        float s1 = s_scale[C_ + c], t1 = s_shift[C_ + c];
        unsigned bit = 1u << j;
        if (fmaf(s0, r0.x, t0) > 0.f) acc[0] |= bit;
        if (fmaf(s0, r0.y, t0) > 0.f) acc[1] |= bit;
        if (fmaf(s0, r1.x, t0) > 0.f) acc[2] |= bit;
        if (fmaf(s0, r1.y, t0) > 0.f) acc[3] |= bit;
        if (fmaf(s1, r0.x, t1) > 0.f) acc[4] |= bit;
        if (fmaf(s1, r0.y, t1) > 0.f) acc[5] |= bit;
        if (fmaf(s1, r1.x, t1) > 0.f) acc[6] |= bit;
        if (fmaf(s1, r1.y, t1) > 0.f) acc[7] |= bit;
    }

#pragma unroll
    for (int br = 0; br < 2; br++)
#pragma unroll
        for (int p = 0; p < 4; p++) {
            int dy = p >> 1, dx = p & 1;
            g_abits[br][wp][b][y0 + dy][dx][lane] = acc[br * 4 + p];
        }
}

// ================= K4: bf16 HMMA conv, register-built A fragments =================
// CTA: M=128 pixels (4 oy x 32 ox), N=192 oc, K=9 taps x 192 ic.
// 512 threads = 16 warps (4M x 4N), warp tile 32x48.
// A fragments built in registers from the resident bit patch (no A smem tile).
// smem: B double buffer 2x192x400B + bit patch 6 planes x 9 rows x 256B.
#define A_ST      400
#define BBUF_B    76800            // 192*400
#define PAT_B     13824            // 6*9*256
#define PAT_OFF   (2 * BBUF_B)
#define CONV_SMEM (PAT_OFF + PAT_B)   // 167424

__global__ void __launch_bounds__(512, 1) k_conv(const float* __restrict__ bias1,
                                                 const float* __restrict__ bias2,
                                                 float* __restrict__ out) {
    extern __shared__ __align__(16) char smem[];
    __shared__ float s_bias[C_];
    uint32_t sb = smem_to_u32(smem);
    const uint32_t sbPAT = sb + PAT_OFF;

    int tid = threadIdx.x;
    int lane = tid & 31, w = tid >> 5;
    int wm = w & 3, wn = w >> 2;
    int g = lane >> 2;            // fragment row group 0..7
    int t2 = (lane & 3) * 2;      // fragment col pair base
    int yg = blockIdx.x, br = blockIdx.y, b = blockIdx.z;
    int oy0 = yg * 4;

    const float* bias = br ? bias2 : bias1;
    if (tid < C_) s_bias[tid] = bias[tid];

    const int8_t* gw8 = (const int8_t*)g_wbf + (size_t)br * 9 * C_ * (C_ * 2);

    // ---- prologue: bit patch (plane-major rows) + B(0) ----
    {
        for (int i = tid; i < 864; i += 512) {
            int wd = i / 144;
            int r = i - wd * 144;
            int ylocal = r / 16;
            int t = r - ylocal * 16;
            int y = 2 * oy0 - 1 + ylocal;
            bool ok = (y >= 0);
            const unsigned* base = &g_abits[br][wd][b][ok ? y : 0][0][0];
            CP_ASYNC16(sbPAT + (uint32_t)((wd * 9 + ylocal) * 256 + t * 16),
                       (const int8_t*)base + t * 16, ok ? 16u : 0u);
        }
        for (int i = tid; i < 4608; i += 512) {
            int oc = i / 24, t = i - oc * 24;
            CP_ASYNC16(sb + (uint32_t)(oc * A_ST + t * 16), gw8 + (size_t)oc * 384 + t * 16, 16u);
        }
        CP_COMMIT();
        CP_WAIT0();
        __syncthreads();
    }

    // ---- B ldmatrix fragment geometry (verified rounds 4-9) ----
    uint32_t boff[3];
    {
        int sub = lane & 7, gg = lane >> 3;
#pragma unroll
        for (int np = 0; np < 3; np++) {
            int row = wn * 48 + np * 16 + sub + ((gg >> 1) << 3);
            int kcol = (gg & 1) * 8;
            boff[np] = (uint32_t)(row * A_ST + kcol * 2);
        }
    }

    float d[2][6][4];
#pragma unroll
    for (int mt = 0; mt < 2; mt++)
#pragma unroll
        for (int nt = 0; nt < 6; nt++)
#pragma unroll
            for (int e = 0; e < 4; e++) d[mt][nt][e] = 0.f;

    for (int tap = 0; tap < 9; tap++) {
        int ky = tap / 3, kx = tap - 3 * (tap / 3);

        // ---- gather this tap's bit rows into registers ----
        int yl = 2 * wm + ky;                      // local patch row 0..8
        bool yok = !(oy0 == 0 && yl == 0);
        int par = (kx != 1) ? 1 : 0;
        uint32_t rb[4][6];
        uint32_t basew[4];
#pragma unroll
        for (int i = 0; i < 4; i++) {
            int ox = g + 8 * i;
            bool ok = yok && !(kx == 0 && ox == 0);
            int j = ox - (kx == 0);
            int jc = j < 0 ? 0 : j;
            uint32_t addr = sbPAT + (uint32_t)(yl * 256 + ((par << 5) + jc) * 4);
#pragma unroll
            for (int wd = 0; wd < 6; wd++) {
                uint32_t v;
                asm volatile("ld.shared.b32 %0, [%1];" : "=r"(v) : "r"(addr + wd * 2304));
                rb[i][wd] = ok ? v : 0u;
            }
            basew[i] = ok ? 0xBF80BF80u : 0u;
        }

        // ---- issue B(tap+1) (overlaps with MMA below) ----
        if (tap < 8) {
            const int8_t* gwn = gw8 + (size_t)(tap + 1) * C_ * 384;
            uint32_t dstB = sb + ((tap + 1) & 1) * BBUF_B;
            for (int i = tid; i < 4608; i += 512) {
                int oc = i / 24, t = i - oc * 24;
                CP_ASYNC16(dstB + (uint32_t)(oc * A_ST + t * 16), gwn + (size_t)oc * 384 + t * 16, 16u);
            }
            CP_COMMIT();
        }

        // ---- MMA: A fragments built in registers, B via ldmatrix ----
        uint32_t bbase = sb + (tap & 1) * BBUF_B;
#pragma unroll
        for (int kc = 0; kc < 12; kc++) {
            int wd = kc >> 1;
            int sh = ((kc & 1) << 4) + t2;
            uint32_t af[2][4];
#pragma unroll
            for (int mt = 0; mt < 2; mt++) {
                uint32_t u0 = rb[2 * mt][wd] >> sh;
                uint32_t u1 = rb[2 * mt + 1][wd] >> sh;
                af[mt][0] = basew[2 * mt]     ^ ((u0 & 1u) << 15) ^ ((u0 & 2u) << 30);
                af[mt][1] = basew[2 * mt + 1] ^ ((u1 & 1u) << 15) ^ ((u1 & 2u) << 30);
                uint32_t v0 = u0 >> 8, v1 = u1 >> 8;
                af[mt][2] = basew[2 * mt]     ^ ((v0 & 1u) << 15) ^ ((v0 & 2u) << 30);
                af[mt][3] = basew[2 * mt + 1] ^ ((v1 & 1u) << 15) ^ ((v1 & 2u) << 30);
            }
            uint32_t bf[3][4];
#pragma unroll
            for (int np = 0; np < 3; np++) LDSM_X4(bf[np], bbase + boff[np] + kc * 32);
#pragma unroll
            for (int mt = 0; mt < 2; mt++)
#pragma unroll
                for (int nt = 0; nt < 6; nt++) {
                    int np = nt >> 1;
                    if (nt & 1) { MMA16816(d[mt][nt], af[mt], bf[np][2], bf[np][3]); }
                    else        { MMA16816(d[mt][nt], af[mt], bf[np][0], bf[np][1]); }
                }
        }

        CP_WAIT0();       // B(tap+1) landed (issued before MMA; overlapped)
        __syncthreads();  // visibility + all warps past MMA(tap)
    }

    // ---- epilogue: transpose via smem, fuse bias+relu+shortcut, coalesced out ----
    float* S = (float*)smem;     // S[c][m], stride 132 floats
#pragma unroll
    for (int mt = 0; mt < 2; mt++)
#pragma unroll
        for (int nt = 0; nt < 6; nt++)
#pragma unroll
            for (int e = 0; e < 4; e++) {
                int m = wm * 32 + mt * 16 + (lane >> 2) + ((e >> 1) << 3);
                int c = wn * 48 + nt * 8 + ((lane & 3) << 1) + (e & 1);
                S[c * 132 + m] = d[mt][nt][e];
            }
    __syncthreads();

    size_t ob = ((size_t)b * (2 * C_) + (size_t)br * C_) * (OH_ * OW_) + (size_t)yg * 128;
    const float* scp = &g_sc[b][0][0][0] + yg * 128;
#pragma unroll
    for (int i = tid; i < 24576; i += 512) {
        int c = i >> 7, m = i & 127;
        float v = S[c * 132 + m] + s_bias[c];
        v = fmaxf(v, 0.f) + scp[(size_t)c * (OH_ * OW_) + m];
        out[ob + (size_t)c * (OH_ * OW_) + m] = v;
    }
}

// ================= launch =================
extern "C" void kernel_launch(void* const* d_in, const int* in_sizes, int n_in,
                              void* d_out, int out_size) {
    const float* x     = (const float*)d_in[0];
    const float* g1    = (const float*)d_in[1];
    const float* b1    = (const float*)d_in[2];
    const float* w1    = (const float*)d_in[3];
    const float* bias1 = (const float*)d_in[4];
    const float* g2    = (const float*)d_in[5];
    const float* b2    = (const float*)d_in[6];
    const float* w2    = (const float*)d_in[7];
    const float* bias2 = (const float*)d_in[8];
    float* out = (float*)d_out;

    cudaFuncSetAttribute(k_conv, cudaFuncAttributeMaxDynamicSharedMemorySize, CONV_SMEM);

    k_stats<<<dim3(C_, 16), 256>>>(x);
    k_wpack<<<(2 * 9 * C_ * (C_ / 2) + 255) / 256, 256>>>(w1, w2);
    k_pack<<<(B_ * OH_ * 6) / 8, 256>>>(x, g1, b1, g2, b2);
    dim3 gconv(OH_ / 4, 2, B_);
    k_conv<<<gconv, 512, CONV_SMEM>>>(bias1, bias2, out);
}

// round 11
// speedup vs baseline: 1.2741x; 1.2741x over previous
#include <cuda_runtime.h>
#include <cstdint>

// Problem constants
#define B_   32
#define C_   192
#define H_   64
#define W_   64
#define OH_  32
#define OW_  32

// -------- device scratch (no mallocs allowed) --------
__device__ float g_psum[16][C_];
__device__ float g_pss[16][C_];
__device__ unsigned g_wbf[2 * 9 * C_ * (C_ / 2)];         // bf16x2 weights [br][tap][oc][ic/2]
__device__ unsigned g_abits[2][6][B_][H_][2][32];         // bits [br][plane][b][y][par][j]
__device__ float    g_sc[B_][C_][OH_][OW_];               // shared avgpool shortcut

// ---------------- PTX helpers (sm_80-compatible) ----------------
__device__ __forceinline__ uint32_t smem_to_u32(const void* p) {
    uint32_t a;
    asm("{ .reg .u64 t; cvta.to.shared.u64 t, %1; cvt.u32.u64 %0, t; }" : "=r"(a) : "l"(p));
    return a;
}
#define CP_ASYNC16(dst, src, sz) \
    asm volatile("cp.async.cg.shared.global [%0], [%1], 16, %2;" \
        :: "r"(dst), "l"(src), "r"(sz) : "memory")
#define CP_COMMIT() asm volatile("cp.async.commit_group;" ::: "memory")
#define CP_WAIT0()  asm volatile("cp.async.wait_group 0;" ::: "memory")
#define LDSM_X4(r, addr) \
    asm volatile("ldmatrix.sync.aligned.m8n8.x4.shared.b16 {%0,%1,%2,%3}, [%4];" \
        : "=r"((r)[0]), "=r"((r)[1]), "=r"((r)[2]), "=r"((r)[3]) : "r"(addr))
#define MMA16816(d, a, b0, b1) \
    asm volatile("mma.sync.aligned.m16n8k16.row.col.f32.bf16.bf16.f32 " \
        "{%0,%1,%2,%3}, {%4,%5,%6,%7}, {%8,%9}, {%0,%1,%2,%3};" \
        : "+f"((d)[0]), "+f"((d)[1]), "+f"((d)[2]), "+f"((d)[3]) \
        : "r"((a)[0]), "r"((a)[1]), "r"((a)[2]), "r"((a)[3]), "r"(b0), "r"(b1))

// ================= K1: per-channel partial sums (16-way) =================
__global__ void k_stats(const float* __restrict__ x) {
    int c = blockIdx.x;
    int s = blockIdx.y;
    int tid = threadIdx.x;
    float sm = 0.f, ss = 0.f;
    for (int b = 2 * s; b < 2 * s + 2; b++) {
        const float4* p = (const float4*)(x + ((size_t)(b * C_ + c)) * (H_ * W_));
#pragma unroll
        for (int i = tid; i < (H_ * W_) / 4; i += 256) {
            float4 v = p[i];
            sm += (v.x + v.y) + (v.z + v.w);
            ss += fmaf(v.x, v.x, v.y * v.y) + fmaf(v.z, v.z, v.w * v.w);
        }
    }
    __shared__ float sh1[256], sh2[256];
    sh1[tid] = sm; sh2[tid] = ss;
    __syncthreads();
    for (int st = 128; st > 0; st >>= 1) {
        if (tid < st) { sh1[tid] += sh1[tid + st]; sh2[tid] += sh2[tid + st]; }
        __syncthreads();
    }
    if (tid == 0) { g_psum[s][c] = sh1[0]; g_pss[s][c] = sh2[0]; }
}

// ================= K2: pack weights to bf16 +-1, [br][tap][oc][ic] =========
__global__ void k_wpack(const float* __restrict__ w1, const float* __restrict__ w2) {
    int i = blockIdx.x * 256 + threadIdx.x;
    if (i >= 2 * 9 * C_ * (C_ / 2)) return;
    int cw = i % (C_ / 2);
    int t = i / (C_ / 2);
    int oc = t % C_; t /= C_;
    int tap = t % 9;
    int br = t / 9;
    int ky = tap / 3, kx = tap % 3;
    const float* w = br ? w2 : w1;
    int c0 = 2 * cw;
    float v0 = w[((oc * C_ + c0) * 3 + ky) * 3 + kx];
    float v1 = w[((oc * C_ + c0 + 1) * 3 + ky) * 3 + kx];
    unsigned lo = v0 > 0.f ? 0x3F80u : 0xBF80u;
    unsigned hi = v1 > 0.f ? 0x3F80u : 0xBF80u;
    g_wbf[i] = lo | (hi << 16);
}

// ========== K3: fused stats-finalize + binarize (plane layout) + avgpool ==========
__global__ void __launch_bounds__(256) k_pack(const float* __restrict__ x,
                                              const float* __restrict__ g1,
                                              const float* __restrict__ b1,
                                              const float* __restrict__ g2,
                                              const float* __restrict__ b2) {
    __shared__ float s_scale[2 * C_], s_shift[2 * C_];
    int tid = threadIdx.x;
    for (int i = tid; i < 2 * C_; i += 256) {
        int br = i / C_, c = i % C_;
        float s = 0.f, q = 0.f;
#pragma unroll
        for (int k = 0; k < 16; k++) { s += g_psum[k][c]; q += g_pss[k][c]; }
        const float invn = 1.f / (float)(B_ * H_ * W_);
        float mu = s * invn;
        float var = q * invn - mu * mu;
        float rstd = rsqrtf(var + 1e-5f);
        float gamma = br ? g2[c] : g1[c];
        float beta  = br ? b2[c] : b1[c];
        float sc = gamma * rstd;
        s_scale[i] = sc;
        s_shift[i] = beta - sc * mu;
    }
    __syncthreads();

    int gw = blockIdx.x * 8 + (tid >> 5);
    int lane = tid & 31;
    int b = gw / (OH_ * 6);
    int rem = gw % (OH_ * 6);
    int oy = rem / 6;
    int wp = rem % 6;
    int c0 = wp * 32;

    const float* px = x + ((size_t)(b * C_ + c0)) * (H_ * W_) + (2 * oy) * W_ + 2 * lane;
    float* psc = &g_sc[b][c0][oy][lane];
    int y0 = 2 * oy;

    unsigned acc[8];
#pragma unroll
    for (int k = 0; k < 8; k++) acc[k] = 0;

#pragma unroll 8
    for (int j = 0; j < 32; j++) {
        int c = c0 + j;
        const float* pc = px + (size_t)j * (H_ * W_);
        float2 r0 = *(const float2*)pc;
        float2 r1 = *(const float2*)(pc + W_);
        psc[(size_t)j * (OH_ * OW_)] = (r0.x + r0.y + r1.x + r1.y) * 0.25f;
        float s0 = s_scale[c],      t0 = s_shift[c];
        float s1 = s_scale[C_ + c], t1 = s_shift[C_ + c];
        unsigned bit = 1u << j;
        if (fmaf(s0, r0.x, t0) > 0.f) acc[0] |= bit;
        if (fmaf(s0, r0.y, t0) > 0.f) acc[1] |= bit;
        if (fmaf(s0, r1.x, t0) > 0.f) acc[2] |= bit;
        if (fmaf(s0, r1.y, t0) > 0.f) acc[3] |= bit;
        if (fmaf(s1, r0.x, t1) > 0.f) acc[4] |= bit;
        if (fmaf(s1, r0.y, t1) > 0.f) acc[5] |= bit;
        if (fmaf(s1, r1.x, t1) > 0.f) acc[6] |= bit;
        if (fmaf(s1, r1.y, t1) > 0.f) acc[7] |= bit;
    }

#pragma unroll
    for (int br = 0; br < 2; br++)
#pragma unroll
        for (int p = 0; p < 4; p++) {
            int dy = p >> 1, dx = p & 1;
            g_abits[br][wp][b][y0 + dy][dx][lane] = acc[br * 4 + p];
        }
}

// ================= K4: bf16 HMMA conv, 2 CTAs/SM + pipelined LDSM =================
// CTA: 256 threads = 8 warps (4M x 2N). M=128 pixels (4 oy x 32 ox), N=96 oc (half).
// A fragments built in registers from resident bit patch; B half-tile double-buffered.
// smem: 2 x 96x400B B buffers + bit patch 6 planes x 9 rows x 256B = 90624 B.
#define A_ST      400
#define BBUF_B    38400            // 96*400
#define PAT_B     13824            // 6*9*256
#define PAT_OFF   (2 * BBUF_B)
#define CONV_SMEM (PAT_OFF + PAT_B)   // 90624

__global__ void __launch_bounds__(256, 2) k_conv(const float* __restrict__ bias1,
                                                 const float* __restrict__ bias2,
                                                 float* __restrict__ out) {
    extern __shared__ __align__(16) char smem[];
    __shared__ float s_bias[96];
    uint32_t sb = smem_to_u32(smem);
    const uint32_t sbPAT = sb + PAT_OFF;

    int tid = threadIdx.x;
    int lane = tid & 31, w = tid >> 5;
    int wm = w & 3, wn = w >> 2;            // wn 0..1
    int g = lane >> 2;                      // fragment row group 0..7
    int t2 = (lane & 3) * 2;                // fragment col pair base
    int yg = blockIdx.x;
    int nh = blockIdx.y & 1, br = blockIdx.y >> 1;
    int b = blockIdx.z;
    int oy0 = yg * 4;
    int ocb = nh * 96;

    const float* bias = br ? bias2 : bias1;
    if (tid < 96) s_bias[tid] = bias[ocb + tid];

    // weight bytes: row (tap*C_ + ocb + ocl)*384
    const int8_t* gw8 = (const int8_t*)g_wbf + ((size_t)br * 9 * C_ + ocb) * 384;

    // ---- prologue: bit patch (plane-major rows) + B(0) half-tile ----
    {
        for (int i = tid; i < 864; i += 256) {
            int wd = i / 144;
            int r = i - wd * 144;
            int ylocal = r / 16;
            int t = r - ylocal * 16;
            int y = 2 * oy0 - 1 + ylocal;
            bool ok = (y >= 0);
            const unsigned* base = &g_abits[br][wd][b][ok ? y : 0][0][0];
            CP_ASYNC16(sbPAT + (uint32_t)((wd * 9 + ylocal) * 256 + t * 16),
                       (const int8_t*)base + t * 16, ok ? 16u : 0u);
        }
        for (int i = tid; i < 2304; i += 256) {
            int oc = i / 24, t = i - oc * 24;
            CP_ASYNC16(sb + (uint32_t)(oc * A_ST + t * 16), gw8 + (size_t)oc * 384 + t * 16, 16u);
        }
        CP_COMMIT();
        CP_WAIT0();
        __syncthreads();
    }

    // ---- B ldmatrix fragment geometry (verified rounds 4-10) ----
    uint32_t boff[3];
    {
        int sub = lane & 7, gg = lane >> 3;
#pragma unroll
        for (int np = 0; np < 3; np++) {
            int row = wn * 48 + np * 16 + sub + ((gg >> 1) << 3);
            int kcol = (gg & 1) * 8;
            boff[np] = (uint32_t)(row * A_ST + kcol * 2);
        }
    }

    float d[2][6][4];
#pragma unroll
    for (int mt = 0; mt < 2; mt++)
#pragma unroll
        for (int nt = 0; nt < 6; nt++)
#pragma unroll
            for (int e = 0; e < 4; e++) d[mt][nt][e] = 0.f;

    for (int tap = 0; tap < 9; tap++) {
        int ky = tap / 3, kx = tap - 3 * (tap / 3);

        // ---- gather this tap's bit rows into registers ----
        int yl = 2 * wm + ky;
        bool yok = !(oy0 == 0 && yl == 0);
        int par = (kx != 1) ? 1 : 0;
        uint32_t rb[4][6];
        uint32_t basew[4];
#pragma unroll
        for (int i = 0; i < 4; i++) {
            int ox = g + 8 * i;
            bool ok = yok && !(kx == 0 && ox == 0);
            int j = ox - (kx == 0);
            int jc = j < 0 ? 0 : j;
            uint32_t addr = sbPAT + (uint32_t)(yl * 256 + ((par << 5) + jc) * 4);
#pragma unroll
            for (int wd = 0; wd < 6; wd++) {
                uint32_t v;
                asm volatile("ld.shared.b32 %0, [%1];" : "=r"(v) : "r"(addr + wd * 2304));
                rb[i][wd] = ok ? v : 0u;
            }
            basew[i] = ok ? 0xBF80BF80u : 0u;
        }

        // ---- issue B(tap+1) (flight overlaps the MMA loop) ----
        if (tap < 8) {
            const int8_t* gwn = gw8 + (size_t)(tap + 1) * C_ * 384;
            uint32_t dstB = sb + ((tap + 1) & 1) * BBUF_B;
            for (int i = tid; i < 2304; i += 256) {
                int oc = i / 24, t = i - oc * 24;
                CP_ASYNC16(dstB + (uint32_t)(oc * A_ST + t * 16), gwn + (size_t)oc * 384 + t * 16, 16u);
            }
            CP_COMMIT();
        }

        // ---- MMA loop with software-pipelined B fragments ----
        uint32_t bbase = sb + (tap & 1) * BBUF_B;
        uint32_t bf[2][3][4];
#pragma unroll
        for (int np = 0; np < 3; np++) LDSM_X4(bf[0][np], bbase + boff[np]);
#pragma unroll
        for (int kc = 0; kc < 12; kc++) {
            int cur = kc & 1;
            if (kc < 11) {
#pragma unroll
                for (int np = 0; np < 3; np++)
                    LDSM_X4(bf[cur ^ 1][np], bbase + boff[np] + (kc + 1) * 32);
            }
            int wd = kc >> 1;
            int sh = ((kc & 1) << 4) + t2;
            uint32_t af[2][4];
#pragma unroll
            for (int mt = 0; mt < 2; mt++) {
                uint32_t u0 = rb[2 * mt][wd] >> sh;
                uint32_t u1 = rb[2 * mt + 1][wd] >> sh;
                af[mt][0] = basew[2 * mt]     ^ ((u0 & 1u) << 15) ^ ((u0 & 2u) << 30);
                af[mt][1] = basew[2 * mt + 1] ^ ((u1 & 1u) << 15) ^ ((u1 & 2u) << 30);
                uint32_t v0 = u0 >> 8, v1 = u1 >> 8;
                af[mt][2] = basew[2 * mt]     ^ ((v0 & 1u) << 15) ^ ((v0 & 2u) << 30);
                af[mt][3] = basew[2 * mt + 1] ^ ((v1 & 1u) << 15) ^ ((v1 & 2u) << 30);
            }
#pragma unroll
            for (int mt = 0; mt < 2; mt++)
#pragma unroll
                for (int nt = 0; nt < 6; nt++) {
                    int np = nt >> 1;
                    if (nt & 1) { MMA16816(d[mt][nt], af[mt], bf[cur][np][2], bf[cur][np][3]); }
                    else        { MMA16816(d[mt][nt], af[mt], bf[cur][np][0], bf[cur][np][1]); }
                }
        }

        CP_WAIT0();       // B(tap+1) landed (issued before MMA; overlapped)
        __syncthreads();  // all warps past MMA(tap) before buffer reuse
    }

    // ---- epilogue: transpose via smem, fuse bias+relu+shortcut, coalesced out ----
    float* S = (float*)smem;     // S[c][m], c local 0..95, stride 132 floats
#pragma unroll
    for (int mt = 0; mt < 2; mt++)
#pragma unroll
        for (int nt = 0; nt < 6; nt++)
#pragma unroll
            for (int e = 0; e < 4; e++) {
                int m = wm * 32 + mt * 16 + (lane >> 2) + ((e >> 1) << 3);
                int c = wn * 48 + nt * 8 + ((lane & 3) << 1) + (e & 1);
                S[c * 132 + m] = d[mt][nt][e];
            }
    __syncthreads();

    size_t ob = ((size_t)b * (2 * C_) + (size_t)br * C_ + ocb) * (OH_ * OW_) + (size_t)yg * 128;
    const float* scp = &g_sc[b][ocb][0][0] + yg * 128;
#pragma unroll
    for (int i = tid; i < 12288; i += 256) {
        int c = i >> 7, m = i & 127;
        float v = S[c * 132 + m] + s_bias[c];
        v = fmaxf(v, 0.f) + scp[(size_t)c * (OH_ * OW_) + m];
        out[ob + (size_t)c * (OH_ * OW_) + m] = v;
    }
}

// ================= launch =================
extern "C" void kernel_launch(void* const* d_in, const int* in_sizes, int n_in,
                              void* d_out, int out_size) {
    const float* x     = (const float*)d_in[0];
    const float* g1    = (const float*)d_in[1];
    const float* b1    = (const float*)d_in[2];
    const float* w1    = (const float*)d_in[3];
    const float* bias1 = (const float*)d_in[4];
    const float* g2    = (const float*)d_in[5];
    const float* b2    = (const float*)d_in[6];
    const float* w2    = (const float*)d_in[7];
    const float* bias2 = (const float*)d_in[8];
    float* out = (float*)d_out;

    cudaFuncSetAttribute(k_conv, cudaFuncAttributeMaxDynamicSharedMemorySize, CONV_SMEM);

    k_stats<<<dim3(C_, 16), 256>>>(x);
    k_wpack<<<(2 * 9 * C_ * (C_ / 2) + 255) / 256, 256>>>(w1, w2);
    k_pack<<<(B_ * OH_ * 6) / 8, 256>>>(x, g1, b1, g2, b2);
    dim3 gconv(OH_ / 4, 4, B_);
    k_conv<<<gconv, 256, CONV_SMEM>>>(bias1, bias2, out);
}

// round 12
// speedup vs baseline: 1.2916x; 1.0138x over previous
#include <cuda_runtime.h>
#include <cstdint>

// Problem constants
#define B_   32
#define C_   192
#define H_   64
#define W_   64
#define OH_  32
#define OW_  32

// -------- device scratch (no mallocs allowed) --------
__device__ float g_psum[16][C_];
__device__ float g_pss[16][C_];
__device__ unsigned g_wbf[2 * 9 * C_ * (C_ / 2)];         // bf16x2 weights [br][tap][oc][ic/2]
__device__ unsigned g_abits[2][6][B_][H_][2][32];         // bits [br][plane][b][y][par][j]
__device__ float    g_sc[B_][C_][OH_][OW_];               // shared avgpool shortcut

// ---------------- PTX helpers (sm_80-compatible) ----------------
__device__ __forceinline__ uint32_t smem_to_u32(const void* p) {
    uint32_t a;
    asm("{ .reg .u64 t; cvta.to.shared.u64 t, %1; cvt.u32.u64 %0, t; }" : "=r"(a) : "l"(p));
    return a;
}
#define CP_ASYNC16(dst, src, sz) \
    asm volatile("cp.async.cg.shared.global [%0], [%1], 16, %2;" \
        :: "r"(dst), "l"(src), "r"(sz) : "memory")
#define CP_COMMIT() asm volatile("cp.async.commit_group;" ::: "memory")
#define CP_WAIT0()  asm volatile("cp.async.wait_group 0;" ::: "memory")
#define LDSM_X4(r, addr) \
    asm volatile("ldmatrix.sync.aligned.m8n8.x4.shared.b16 {%0,%1,%2,%3}, [%4];" \
        : "=r"((r)[0]), "=r"((r)[1]), "=r"((r)[2]), "=r"((r)[3]) : "r"(addr))
#define MMA16816(d, a, b0, b1) \
    asm volatile("mma.sync.aligned.m16n8k16.row.col.f32.bf16.bf16.f32 " \
        "{%0,%1,%2,%3}, {%4,%5,%6,%7}, {%8,%9}, {%0,%1,%2,%3};" \
        : "+f"((d)[0]), "+f"((d)[1]), "+f"((d)[2]), "+f"((d)[3]) \
        : "r"((a)[0]), "r"((a)[1]), "r"((a)[2]), "r"((a)[3]), "r"(b0), "r"(b1))

// ================= K1: per-channel partial sums (16-way) =================
__global__ void k_stats(const float* __restrict__ x) {
    int c = blockIdx.x;
    int s = blockIdx.y;
    int tid = threadIdx.x;
    float sm = 0.f, ss = 0.f;
    for (int b = 2 * s; b < 2 * s + 2; b++) {
        const float4* p = (const float4*)(x + ((size_t)(b * C_ + c)) * (H_ * W_));
#pragma unroll
        for (int i = tid; i < (H_ * W_) / 4; i += 256) {
            float4 v = p[i];
            sm += (v.x + v.y) + (v.z + v.w);
            ss += fmaf(v.x, v.x, v.y * v.y) + fmaf(v.z, v.z, v.w * v.w);
        }
    }
    __shared__ float sh1[256], sh2[256];
    sh1[tid] = sm; sh2[tid] = ss;
    __syncthreads();
    for (int st = 128; st > 0; st >>= 1) {
        if (tid < st) { sh1[tid] += sh1[tid + st]; sh2[tid] += sh2[tid + st]; }
        __syncthreads();
    }
    if (tid == 0) { g_psum[s][c] = sh1[0]; g_pss[s][c] = sh2[0]; }
}

// ================= K2: pack weights to bf16 +-1, [br][tap][oc][ic] =========
__global__ void k_wpack(const float* __restrict__ w1, const float* __restrict__ w2) {
    int i = blockIdx.x * 256 + threadIdx.x;
    if (i >= 2 * 9 * C_ * (C_ / 2)) return;
    int cw = i % (C_ / 2);
    int t = i / (C_ / 2);
    int oc = t % C_; t /= C_;
    int tap = t % 9;
    int br = t / 9;
    int ky = tap / 3, kx = tap % 3;
    const float* w = br ? w2 : w1;
    int c0 = 2 * cw;
    float v0 = w[((oc * C_ + c0) * 3 + ky) * 3 + kx];
    float v1 = w[((oc * C_ + c0 + 1) * 3 + ky) * 3 + kx];
    unsigned lo = v0 > 0.f ? 0x3F80u : 0xBF80u;
    unsigned hi = v1 > 0.f ? 0x3F80u : 0xBF80u;
    g_wbf[i] = lo | (hi << 16);
}

// ========== K3: fused stats-finalize + binarize (plane layout) + avgpool ==========
__global__ void __launch_bounds__(256) k_pack(const float* __restrict__ x,
                                              const float* __restrict__ g1,
                                              const float* __restrict__ b1,
                                              const float* __restrict__ g2,
                                              const float* __restrict__ b2) {
    __shared__ float s_scale[2 * C_], s_shift[2 * C_];
    int tid = threadIdx.x;
    for (int i = tid; i < 2 * C_; i += 256) {
        int br = i / C_, c = i % C_;
        float s = 0.f, q = 0.f;
#pragma unroll
        for (int k = 0; k < 16; k++) { s += g_psum[k][c]; q += g_pss[k][c]; }
        const float invn = 1.f / (float)(B_ * H_ * W_);
        float mu = s * invn;
        float var = q * invn - mu * mu;
        float rstd = rsqrtf(var + 1e-5f);
        float gamma = br ? g2[c] : g1[c];
        float beta  = br ? b2[c] : b1[c];
        float sc = gamma * rstd;
        s_scale[i] = sc;
        s_shift[i] = beta - sc * mu;
    }
    __syncthreads();

    int gw = blockIdx.x * 8 + (tid >> 5);
    int lane = tid & 31;
    int b = gw / (OH_ * 6);
    int rem = gw % (OH_ * 6);
    int oy = rem / 6;
    int wp = rem % 6;
    int c0 = wp * 32;

    const float* px = x + ((size_t)(b * C_ + c0)) * (H_ * W_) + (2 * oy) * W_ + 2 * lane;
    float* psc = &g_sc[b][c0][oy][lane];
    int y0 = 2 * oy;

    unsigned acc[8];
#pragma unroll
    for (int k = 0; k < 8; k++) acc[k] = 0;

#pragma unroll 8
    for (int j = 0; j < 32; j++) {
        int c = c0 + j;
        const float* pc = px + (size_t)j * (H_ * W_);
        float2 r0 = *(const float2*)pc;
        float2 r1 = *(const float2*)(pc + W_);
        psc[(size_t)j * (OH_ * OW_)] = (r0.x + r0.y + r1.x + r1.y) * 0.25f;
        float s0 = s_scale[c],      t0 = s_shift[c];
        float s1 = s_scale[C_ + c], t1 = s_shift[C_ + c];
        unsigned bit = 1u << j;
        if (fmaf(s0, r0.x, t0) > 0.f) acc[0] |= bit;
        if (fmaf(s0, r0.y, t0) > 0.f) acc[1] |= bit;
        if (fmaf(s0, r1.x, t0) > 0.f) acc[2] |= bit;
        if (fmaf(s0, r1.y, t0) > 0.f) acc[3] |= bit;
        if (fmaf(s1, r0.x, t1) > 0.f) acc[4] |= bit;
        if (fmaf(s1, r0.y, t1) > 0.f) acc[5] |= bit;
        if (fmaf(s1, r1.x, t1) > 0.f) acc[6] |= bit;
        if (fmaf(s1, r1.y, t1) > 0.f) acc[7] |= bit;
    }

#pragma unroll
    for (int br = 0; br < 2; br++)
#pragma unroll
        for (int p = 0; p < 4; p++) {
            int dy = p >> 1, dx = p & 1;
            g_abits[br][wp][b][y0 + dy][dx][lane] = acc[br * 4 + p];
        }
}

// ================= K4: bf16 HMMA conv, 3 CTAs/SM, 16-row warp tiles =================
// CTA: 256 threads = 8 warps (4M x 2N). M=64 pixels (2 oy x 32 ox), N=96 oc.
// Warp tile 16x48. A fragments built in registers (IMAD bit-spread trick).
// smem: single B buffer 96x400B + bit patch 6 planes x 5 rows x 256B = 46080 B.
#define A_ST      400
#define BBUF_B    38400            // 96*400
#define PAT_B     7680             // 6*5*256
#define PAT_OFF   BBUF_B
#define CONV_SMEM (BBUF_B + PAT_B) // 46080

__global__ void __launch_bounds__(256, 3) k_conv(const float* __restrict__ bias1,
                                                 const float* __restrict__ bias2,
                                                 float* __restrict__ out) {
    extern __shared__ __align__(16) char smem[];
    __shared__ float s_bias[96];
    uint32_t sb = smem_to_u32(smem);
    const uint32_t sbPAT = sb + PAT_OFF;

    int tid = threadIdx.x;
    int lane = tid & 31, w = tid >> 5;
    int wm = w & 3, wn = w >> 2;            // 4M x 2N warp grid
    int g = lane >> 2;                      // fragment row group 0..7
    int t2 = (lane & 3) * 2;                // fragment col pair base
    int yg = blockIdx.x;                    // 0..15 (2 oy rows each)
    int nh = blockIdx.y & 1, br = blockIdx.y >> 1;
    int b = blockIdx.z;
    int oy0 = yg * 2;
    int ocb = nh * 96;

    const float* bias = br ? bias2 : bias1;
    if (tid < 96) s_bias[tid] = bias[ocb + tid];

    const int8_t* gw8 = (const int8_t*)g_wbf + ((size_t)br * 9 * C_ + ocb) * 384;

    // ---- prologue: bit patch (5 y rows) + B(0) ----
    {
        for (int i = tid; i < 480; i += 256) {
            int wd = i / 80;
            int r = i - wd * 80;
            int ylocal = r / 16;
            int t = r - ylocal * 16;
            int y = 2 * oy0 - 1 + ylocal;
            bool ok = (y >= 0);
            const unsigned* base = &g_abits[br][wd][b][ok ? y : 0][0][0];
            CP_ASYNC16(sbPAT + (uint32_t)((wd * 5 + ylocal) * 256 + t * 16),
                       (const int8_t*)base + t * 16, ok ? 16u : 0u);
        }
        for (int i = tid; i < 2304; i += 256) {
            int oc = i / 24, t = i - oc * 24;
            CP_ASYNC16(sb + (uint32_t)(oc * A_ST + t * 16), gw8 + (size_t)oc * 384 + t * 16, 16u);
        }
        CP_COMMIT();
        CP_WAIT0();
        __syncthreads();
    }

    // ---- B ldmatrix fragment geometry (verified rounds 4-11) ----
    uint32_t boff[3];
    {
        int sub = lane & 7, gg = lane >> 3;
#pragma unroll
        for (int np = 0; np < 3; np++) {
            int row = wn * 48 + np * 16 + sub + ((gg >> 1) << 3);
            int kcol = (gg & 1) * 8;
            boff[np] = (uint32_t)(row * A_ST + kcol * 2);
        }
    }

    float d[6][4];
#pragma unroll
    for (int nt = 0; nt < 6; nt++)
#pragma unroll
        for (int e = 0; e < 4; e++) d[nt][e] = 0.f;

    int r_oy = wm >> 1;                      // local oy row 0..1
    int oxbase = (wm & 1) * 16 + g;          // + 8*i gives ox

    for (int tap = 0; tap < 9; tap++) {
        int ky = tap / 3, kx = tap - 3 * (tap / 3);

        // ---- gather this tap's bit rows into registers ----
        int yl = 2 * r_oy + ky;              // patch local row 0..4
        bool yok = !(oy0 == 0 && yl == 0);
        int par = (kx != 1) ? 1 : 0;
        uint32_t rb[2][6];
        uint32_t basew[2];
#pragma unroll
        for (int i = 0; i < 2; i++) {
            int ox = oxbase + 8 * i;
            bool ok = yok && !(kx == 0 && ox == 0);
            int j = ox - (kx == 0);
            int jc = j < 0 ? 0 : j;
            uint32_t addr = sbPAT + (uint32_t)(yl * 256 + ((par << 5) + jc) * 4);
#pragma unroll
            for (int wd = 0; wd < 6; wd++) {
                uint32_t v;
                asm volatile("ld.shared.b32 %0, [%1];" : "=r"(v) : "r"(addr + wd * 1280));
                rb[i][wd] = ok ? v : 0u;
            }
            basew[i] = ok ? 0xBF80BF80u : 0u;
        }

        // ---- wait for B(tap) (issued at end of previous tap / prologue) ----
        if (tap > 0) {
            CP_WAIT0();
            __syncthreads();
        }

        // ---- MMA loop with software-pipelined B fragments ----
        uint32_t bf[2][3][4];
#pragma unroll
        for (int np = 0; np < 3; np++) LDSM_X4(bf[0][np], sb + boff[np]);
#pragma unroll
        for (int kc = 0; kc < 12; kc++) {
            int cur = kc & 1;
            if (kc < 11) {
#pragma unroll
                for (int np = 0; np < 3; np++)
                    LDSM_X4(bf[cur ^ 1][np], sb + boff[np] + (kc + 1) * 32);
            }
            int wd = kc >> 1;
            uint32_t sh2 = (uint32_t)(((kc & 1) << 4) + t2);
            uint32_t af[4];
            {
                uint32_t m0 = (rb[0][wd] >> sh2) & 0x303u;
                uint32_t m1 = (rb[1][wd] >> sh2) & 0x303u;
                af[0] = ((m0 * 0x40008000u) & 0x80008000u) ^ basew[0];
                af[1] = ((m1 * 0x40008000u) & 0x80008000u) ^ basew[1];
                af[2] = (((m0 >> 8) * 0x40008000u) & 0x80008000u) ^ basew[0];
                af[3] = (((m1 >> 8) * 0x40008000u) & 0x80008000u) ^ basew[1];
            }
#pragma unroll
            for (int nt = 0; nt < 6; nt++) {
                int np = nt >> 1;
                if (nt & 1) { MMA16816(d[nt], af, bf[cur][np][2], bf[cur][np][3]); }
                else        { MMA16816(d[nt], af, bf[cur][np][0], bf[cur][np][1]); }
            }
        }

        __syncthreads();   // all warps done reading B(tap) before overwrite

        // ---- issue B(tap+1) into the single buffer ----
        if (tap < 8) {
            const int8_t* gwn = gw8 + (size_t)(tap + 1) * C_ * 384;
            for (int i = tid; i < 2304; i += 256) {
                int oc = i / 24, t = i - oc * 24;
                CP_ASYNC16(sb + (uint32_t)(oc * A_ST + t * 16), gwn + (size_t)oc * 384 + t * 16, 16u);
            }
            CP_COMMIT();
        }
    }

    // ---- epilogue: transpose via smem, fuse bias+relu+shortcut, coalesced out ----
    float* S = (float*)smem;     // S[c][m], c 0..95, m 0..63, stride 68 floats
#pragma unroll
    for (int nt = 0; nt < 6; nt++)
#pragma unroll
        for (int e = 0; e < 4; e++) {
            int m = wm * 16 + (lane >> 2) + ((e >> 1) << 3);
            int c = wn * 48 + nt * 8 + ((lane & 3) << 1) + (e & 1);
            S[c * 68 + m] = d[nt][e];
        }
    __syncthreads();

    size_t ob = ((size_t)b * (2 * C_) + (size_t)br * C_ + ocb) * (OH_ * OW_) + (size_t)yg * 64;
    const float* scp = &g_sc[b][ocb][0][0] + yg * 64;
#pragma unroll
    for (int i = tid; i < 6144; i += 256) {
        int c = i >> 6, m = i & 63;
        float v = S[c * 68 + m] + s_bias[c];
        v = fmaxf(v, 0.f) + scp[(size_t)c * (OH_ * OW_) + m];
        out[ob + (size_t)c * (OH_ * OW_) + m] = v;
    }
}

// ================= launch =================
extern "C" void kernel_launch(void* const* d_in, const int* in_sizes, int n_in,
                              void* d_out, int out_size) {
    const float* x     = (const float*)d_in[0];
    const float* g1    = (const float*)d_in[1];
    const float* b1    = (const float*)d_in[2];
    const float* w1    = (const float*)d_in[3];
    const float* bias1 = (const float*)d_in[4];
    const float* g2    = (const float*)d_in[5];
    const float* b2    = (const float*)d_in[6];
    const float* w2    = (const float*)d_in[7];
    const float* bias2 = (const float*)d_in[8];
    float* out = (float*)d_out;

    cudaFuncSetAttribute(k_conv, cudaFuncAttributeMaxDynamicSharedMemorySize, CONV_SMEM);

    k_stats<<<dim3(C_, 16), 256>>>(x);
    k_wpack<<<(2 * 9 * C_ * (C_ / 2) + 255) / 256, 256>>>(w1, w2);
    k_pack<<<(B_ * OH_ * 6) / 8, 256>>>(x, g1, b1, g2, b2);
    dim3 gconv(16, 4, B_);
    k_conv<<<gconv, 256, CONV_SMEM>>>(bias1, bias2, out);
}

// round 13
// speedup vs baseline: 1.2952x; 1.0028x over previous
#include <cuda_runtime.h>
#include <cstdint>

// Problem constants
#define B_   32
#define C_   192
#define H_   64
#define W_   64
#define OH_  32
#define OW_  32

// -------- device scratch (no mallocs allowed) --------
__device__ float g_psum[16][C_];
__device__ float g_pss[16][C_];
__device__ unsigned g_wbf[2 * 9 * C_ * (C_ / 2)];         // bf16x2 weights [br][tap][oc][ic/2]
__device__ unsigned g_abits[2][6][B_][H_][2][32];         // bits [br][plane][b][y][par][j]
__device__ float    g_sc[B_][C_][OH_][OW_];               // shared avgpool shortcut

// ---------------- PTX helpers (sm_80-compatible) ----------------
__device__ __forceinline__ uint32_t smem_to_u32(const void* p) {
    uint32_t a;
    asm("{ .reg .u64 t; cvta.to.shared.u64 t, %1; cvt.u32.u64 %0, t; }" : "=r"(a) : "l"(p));
    return a;
}
#define CP_ASYNC16(dst, src, sz) \
    asm volatile("cp.async.cg.shared.global [%0], [%1], 16, %2;" \
        :: "r"(dst), "l"(src), "r"(sz) : "memory")
#define CP_COMMIT() asm volatile("cp.async.commit_group;" ::: "memory")
#define CP_WAIT1()  asm volatile("cp.async.wait_group 1;" ::: "memory")
#define CP_WAIT0()  asm volatile("cp.async.wait_group 0;" ::: "memory")
#define LDSM_X4(r, addr) \
    asm volatile("ldmatrix.sync.aligned.m8n8.x4.shared.b16 {%0,%1,%2,%3}, [%4];" \
        : "=r"((r)[0]), "=r"((r)[1]), "=r"((r)[2]), "=r"((r)[3]) : "r"(addr))
#define MMA16816(d, a, b0, b1) \
    asm volatile("mma.sync.aligned.m16n8k16.row.col.f32.bf16.bf16.f32 " \
        "{%0,%1,%2,%3}, {%4,%5,%6,%7}, {%8,%9}, {%0,%1,%2,%3};" \
        : "+f"((d)[0]), "+f"((d)[1]), "+f"((d)[2]), "+f"((d)[3]) \
        : "r"((a)[0]), "r"((a)[1]), "r"((a)[2]), "r"((a)[3]), "r"(b0), "r"(b1))

// ================= K1: per-channel partial sums (16-way) =================
__global__ void k_stats(const float* __restrict__ x) {
    int c = blockIdx.x;
    int s = blockIdx.y;
    int tid = threadIdx.x;
    float sm = 0.f, ss = 0.f;
    for (int b = 2 * s; b < 2 * s + 2; b++) {
        const float4* p = (const float4*)(x + ((size_t)(b * C_ + c)) * (H_ * W_));
#pragma unroll
        for (int i = tid; i < (H_ * W_) / 4; i += 256) {
            float4 v = p[i];
            sm += (v.x + v.y) + (v.z + v.w);
            ss += fmaf(v.x, v.x, v.y * v.y) + fmaf(v.z, v.z, v.w * v.w);
        }
    }
    __shared__ float sh1[256], sh2[256];
    sh1[tid] = sm; sh2[tid] = ss;
    __syncthreads();
    for (int st = 128; st > 0; st >>= 1) {
        if (tid < st) { sh1[tid] += sh1[tid + st]; sh2[tid] += sh2[tid + st]; }
        __syncthreads();
    }
    if (tid == 0) { g_psum[s][c] = sh1[0]; g_pss[s][c] = sh2[0]; }
}

// ================= K2: pack weights to bf16 +-1, [br][tap][oc][ic] =========
__global__ void k_wpack(const float* __restrict__ w1, const float* __restrict__ w2) {
    int i = blockIdx.x * 256 + threadIdx.x;
    if (i >= 2 * 9 * C_ * (C_ / 2)) return;
    int cw = i % (C_ / 2);
    int t = i / (C_ / 2);
    int oc = t % C_; t /= C_;
    int tap = t % 9;
    int br = t / 9;
    int ky = tap / 3, kx = tap % 3;
    const float* w = br ? w2 : w1;
    int c0 = 2 * cw;
    float v0 = w[((oc * C_ + c0) * 3 + ky) * 3 + kx];
    float v1 = w[((oc * C_ + c0 + 1) * 3 + ky) * 3 + kx];
    unsigned lo = v0 > 0.f ? 0x3F80u : 0xBF80u;
    unsigned hi = v1 > 0.f ? 0x3F80u : 0xBF80u;
    g_wbf[i] = lo | (hi << 16);
}

// ========== K3: fused stats-finalize + binarize (plane layout) + avgpool ==========
__global__ void __launch_bounds__(256) k_pack(const float* __restrict__ x,
                                              const float* __restrict__ g1,
                                              const float* __restrict__ b1,
                                              const float* __restrict__ g2,
                                              const float* __restrict__ b2) {
    __shared__ float s_scale[2 * C_], s_shift[2 * C_];
    int tid = threadIdx.x;
    for (int i = tid; i < 2 * C_; i += 256) {
        int br = i / C_, c = i % C_;
        float s = 0.f, q = 0.f;
#pragma unroll
        for (int k = 0; k < 16; k++) { s += g_psum[k][c]; q += g_pss[k][c]; }
        const float invn = 1.f / (float)(B_ * H_ * W_);
        float mu = s * invn;
        float var = q * invn - mu * mu;
        float rstd = rsqrtf(var + 1e-5f);
        float gamma = br ? g2[c] : g1[c];
        float beta  = br ? b2[c] : b1[c];
        float sc = gamma * rstd;
        s_scale[i] = sc;
        s_shift[i] = beta - sc * mu;
    }
    __syncthreads();

    int gw = blockIdx.x * 8 + (tid >> 5);
    int lane = tid & 31;
    int b = gw / (OH_ * 6);
    int rem = gw % (OH_ * 6);
    int oy = rem / 6;
    int wp = rem % 6;
    int c0 = wp * 32;

    const float* px = x + ((size_t)(b * C_ + c0)) * (H_ * W_) + (2 * oy) * W_ + 2 * lane;
    float* psc = &g_sc[b][c0][oy][lane];
    int y0 = 2 * oy;

    unsigned acc[8];
#pragma unroll
    for (int k = 0; k < 8; k++) acc[k] = 0;

#pragma unroll 8
    for (int j = 0; j < 32; j++) {
        int c = c0 + j;
        const float* pc = px + (size_t)j * (H_ * W_);
        float2 r0 = *(const float2*)pc;
        float2 r1 = *(const float2*)(pc + W_);
        psc[(size_t)j * (OH_ * OW_)] = (r0.x + r0.y + r1.x + r1.y) * 0.25f;
        float s0 = s_scale[c],      t0 = s_shift[c];
        float s1 = s_scale[C_ + c], t1 = s_shift[C_ + c];
        unsigned bit = 1u << j;
        if (fmaf(s0, r0.x, t0) > 0.f) acc[0] |= bit;
        if (fmaf(s0, r0.y, t0) > 0.f) acc[1] |= bit;
        if (fmaf(s0, r1.x, t0) > 0.f) acc[2] |= bit;
        if (fmaf(s0, r1.y, t0) > 0.f) acc[3] |= bit;
        if (fmaf(s1, r0.x, t1) > 0.f) acc[4] |= bit;
        if (fmaf(s1, r0.y, t1) > 0.f) acc[5] |= bit;
        if (fmaf(s1, r1.x, t1) > 0.f) acc[6] |= bit;
        if (fmaf(s1, r1.y, t1) > 0.f) acc[7] |= bit;
    }

#pragma unroll
    for (int br = 0; br < 2; br++)
#pragma unroll
        for (int p = 0; p < 4; p++) {
            int dy = p >> 1, dx = p & 1;
            g_abits[br][wp][b][y0 + dy][dx][lane] = acc[br * 4 + p];
        }
}

// ================= K4: bf16 HMMA conv, 4 CTAs/SM, half-K chunk pipeline =====
// CTA: 256 threads = 8 warps (4M x 2N). M=64 pixels (2 oy x 32 ox), N=96 oc.
// Warp tile 16x48. A fragments in registers (IMAD bit-spread).
// B streamed per (tap, half-K chunk): 18 chunks of 96x192B, double-buffered
// via cp.async groups so chunk(t+1) is in flight during MMA(t).
// smem: 2 x 96x208B chunk buffers + bit patch 6 planes x 5 rows x 256B.
#define BCH_ST    208              // chunk row stride (96 k-bytes x2 + pad)
#define BCH_B     19968            // 96*208
#define PAT_B     7680             // 6*5*256
#define PAT_OFF   (2 * BCH_B)
#define CONV_SMEM (PAT_OFF + PAT_B)   // 47616

__global__ void __launch_bounds__(256, 4) k_conv(const float* __restrict__ bias1,
                                                 const float* __restrict__ bias2,
                                                 float* __restrict__ out) {
    extern __shared__ __align__(16) char smem[];
    __shared__ float s_bias[96];
    uint32_t sb = smem_to_u32(smem);
    const uint32_t sbPAT = sb + PAT_OFF;

    int tid = threadIdx.x;
    int lane = tid & 31, w = tid >> 5;
    int wm = w & 3, wn = w >> 2;            // 4M x 2N warp grid
    int g = lane >> 2;                      // fragment row group 0..7
    int t2 = (lane & 3) * 2;                // fragment col pair base
    int yg = blockIdx.x;                    // 0..15 (2 oy rows each)
    int nh = blockIdx.y & 1, br = blockIdx.y >> 1;
    int b = blockIdx.z;
    int oy0 = yg * 2;
    int ocb = nh * 96;

    const float* bias = br ? bias2 : bias1;
    if (tid < 96) s_bias[tid] = bias[ocb + tid];

    const int8_t* gw8 = (const int8_t*)g_wbf + ((size_t)br * 9 * C_ + ocb) * 384;

    // ---- prologue: patch + chunk0 (group0), chunk1 (group1) ----
    {
        for (int i = tid; i < 480; i += 256) {
            int wd = i / 80;
            int r = i - wd * 80;
            int ylocal = r / 16;
            int t = r - ylocal * 16;
            int y = 2 * oy0 - 1 + ylocal;
            bool ok = (y >= 0);
            const unsigned* base = &g_abits[br][wd][b][ok ? y : 0][0][0];
            CP_ASYNC16(sbPAT + (uint32_t)((wd * 5 + ylocal) * 256 + t * 16),
                       (const int8_t*)base + t * 16, ok ? 16u : 0u);
        }
        for (int i = tid; i < 1152; i += 256) {        // tap0 chunk0
            int oc = i / 12, t = i - oc * 12;
            CP_ASYNC16(sb + (uint32_t)(oc * BCH_ST + t * 16),
                       gw8 + (size_t)oc * 384 + t * 16, 16u);
        }
        CP_COMMIT();                                    // G0
        for (int i = tid; i < 1152; i += 256) {        // tap0 chunk1
            int oc = i / 12, t = i - oc * 12;
            CP_ASYNC16(sb + BCH_B + (uint32_t)(oc * BCH_ST + t * 16),
                       gw8 + (size_t)oc * 384 + 192 + t * 16, 16u);
        }
        CP_COMMIT();                                    // G1
    }

    // ---- B ldmatrix fragment geometry (chunk stride 208) ----
    uint32_t boff[3];
    {
        int sub = lane & 7, gg = lane >> 3;
#pragma unroll
        for (int np = 0; np < 3; np++) {
            int row = wn * 48 + np * 16 + sub + ((gg >> 1) << 3);
            int kcol = (gg & 1) * 8;
            boff[np] = (uint32_t)(row * BCH_ST + kcol * 2);
        }
    }

    float d[6][4];
#pragma unroll
    for (int nt = 0; nt < 6; nt++)
#pragma unroll
        for (int e = 0; e < 4; e++) d[nt][e] = 0.f;

    int r_oy = wm >> 1;                      // local oy row 0..1
    int oxbase = (wm & 1) * 16 + g;          // + 8*i gives ox

    for (int it = 0; it < 18; it++) {
        int tap = it >> 1, ch = it & 1;
        int ky = tap / 3, kx = tap - 3 * (tap / 3);

        // ---- wait: chunk(it) landed (chunk(it+1) may be in flight) ----
        if (it < 17) { CP_WAIT1(); } else { CP_WAIT0(); }
        __syncthreads();

        // ---- gather this (tap, chunk)'s bit words into registers ----
        int yl = 2 * r_oy + ky;              // patch local row 0..4
        bool yok = !(oy0 == 0 && yl == 0);
        int par = (kx != 1) ? 1 : 0;
        uint32_t rb[2][3];
        uint32_t basew[2];
#pragma unroll
        for (int i = 0; i < 2; i++) {
            int ox = oxbase + 8 * i;
            bool ok = yok && !(kx == 0 && ox == 0);
            int j = ox - (kx == 0);
            int jc = j < 0 ? 0 : j;
            uint32_t addr = sbPAT + (uint32_t)(yl * 256 + ((par << 5) + jc) * 4)
                          + (uint32_t)(3 * ch) * 1280u;
#pragma unroll
            for (int wdl = 0; wdl < 3; wdl++) {
                uint32_t v;
                asm volatile("ld.shared.b32 %0, [%1];" : "=r"(v) : "r"(addr + wdl * 1280));
                rb[i][wdl] = ok ? v : 0u;
            }
            basew[i] = ok ? 0xBF80BF80u : 0u;
        }

        // ---- MMA over this chunk's 6 k-steps ----
        uint32_t bbase = sb + (uint32_t)(it & 1) * BCH_B;
#pragma unroll
        for (int kcl = 0; kcl < 6; kcl++) {
            uint32_t bf[3][4];
#pragma unroll
            for (int np = 0; np < 3; np++) LDSM_X4(bf[np], bbase + boff[np] + kcl * 32);
            int wdl = kcl >> 1;
            uint32_t sh2 = (uint32_t)(((kcl & 1) << 4) + t2);
            uint32_t af[4];
            {
                uint32_t m0 = (rb[0][wdl] >> sh2) & 0x303u;
                uint32_t m1 = (rb[1][wdl] >> sh2) & 0x303u;
                af[0] = ((m0 * 0x40008000u) & 0x80008000u) ^ basew[0];
                af[1] = ((m1 * 0x40008000u) & 0x80008000u) ^ basew[1];
                af[2] = (((m0 >> 8) * 0x40008000u) & 0x80008000u) ^ basew[0];
                af[3] = (((m1 >> 8) * 0x40008000u) & 0x80008000u) ^ basew[1];
            }
#pragma unroll
            for (int nt = 0; nt < 6; nt++) {
                int np = nt >> 1;
                if (nt & 1) { MMA16816(d[nt], af, bf[np][2], bf[np][3]); }
                else        { MMA16816(d[nt], af, bf[np][0], bf[np][1]); }
            }
        }

        __syncthreads();   // all warps done reading chunk(it) before its buffer reuse

        // ---- issue chunk(it+2) into the buffer just freed ----
        if (it < 16) {
            int tap2 = (it + 2) >> 1, ch2 = (it + 2) & 1;
            const int8_t* gwn = gw8 + (size_t)tap2 * C_ * 384 + ch2 * 192;
            uint32_t dstB = sb + (uint32_t)(it & 1) * BCH_B;
            for (int i = tid; i < 1152; i += 256) {
                int oc = i / 12, t = i - oc * 12;
                CP_ASYNC16(dstB + (uint32_t)(oc * BCH_ST + t * 16),
                           gwn + (size_t)oc * 384 + t * 16, 16u);
            }
            CP_COMMIT();
        }
    }

    // ---- epilogue: transpose via smem, fuse bias+relu+shortcut, coalesced out ----
    float* S = (float*)smem;     // S[c][m], c 0..95, m 0..63, stride 68 floats
    __syncthreads();
#pragma unroll
    for (int nt = 0; nt < 6; nt++)
#pragma unroll
        for (int e = 0; e < 4; e++) {
            int m = wm * 16 + (lane >> 2) + ((e >> 1) << 3);
            int c = wn * 48 + nt * 8 + ((lane & 3) << 1) + (e & 1);
            S[c * 68 + m] = d[nt][e];
        }
    __syncthreads();

    size_t ob = ((size_t)b * (2 * C_) + (size_t)br * C_ + ocb) * (OH_ * OW_) + (size_t)yg * 64;
    const float* scp = &g_sc[b][ocb][0][0] + yg * 64;
#pragma unroll
    for (int i = tid; i < 6144; i += 256) {
        int c = i >> 6, m = i & 63;
        float v = S[c * 68 + m] + s_bias[c];
        v = fmaxf(v, 0.f) + scp[(size_t)c * (OH_ * OW_) + m];
        out[ob + (size_t)c * (OH_ * OW_) + m] = v;
    }
}

// ================= launch =================
extern "C" void kernel_launch(void* const* d_in, const int* in_sizes, int n_in,
                              void* d_out, int out_size) {
    const float* x     = (const float*)d_in[0];
    const float* g1    = (const float*)d_in[1];
    const float* b1    = (const float*)d_in[2];
    const float* w1    = (const float*)d_in[3];
    const float* bias1 = (const float*)d_in[4];
    const float* g2    = (const float*)d_in[5];
    const float* b2    = (const float*)d_in[6];
    const float* w2    = (const float*)d_in[7];
    const float* bias2 = (const float*)d_in[8];
    float* out = (float*)d_out;

    cudaFuncSetAttribute(k_conv, cudaFuncAttributeMaxDynamicSharedMemorySize, CONV_SMEM);

    k_stats<<<dim3(C_, 16), 256>>>(x);
    k_wpack<<<(2 * 9 * C_ * (C_ / 2) + 255) / 256, 256>>>(w1, w2);
    k_pack<<<(B_ * OH_ * 6) / 8, 256>>>(x, g1, b1, g2, b2);
    dim3 gconv(16, 4, B_);
    k_conv<<<gconv, 256, CONV_SMEM>>>(bias1, bias2, out);
}

// round 14
// speedup vs baseline: 1.3332x; 1.0293x over previous
#include <cuda_runtime.h>
#include <cstdint>

// Problem constants
#define B_   32
#define C_   192
#define H_   64
#define W_   64
#define OH_  32
#define OW_  32

// -------- device scratch (no mallocs allowed) --------
__device__ float g_psum[32][C_];
__device__ float g_pss[32][C_];
__device__ float g_scale[2][C_];
__device__ float g_shift[2][C_];
__device__ unsigned g_wbf[2 * 9 * C_ * (C_ / 2)];         // bf16x2 weights [br][tap][oc][ic/2]
__device__ unsigned g_abits[2][6][B_][H_][64];            // bits [br][plane][b][y][j*2+par]
__device__ float    g_sc[B_][C_][OH_][OW_];               // shared avgpool shortcut

// ---------------- PTX helpers (sm_80-compatible) ----------------
__device__ __forceinline__ uint32_t smem_to_u32(const void* p) {
    uint32_t a;
    asm("{ .reg .u64 t; cvta.to.shared.u64 t, %1; cvt.u32.u64 %0, t; }" : "=r"(a) : "l"(p));
    return a;
}
#define CP_ASYNC16(dst, src, sz) \
    asm volatile("cp.async.cg.shared.global [%0], [%1], 16, %2;" \
        :: "r"(dst), "l"(src), "r"(sz) : "memory")
#define CP_COMMIT() asm volatile("cp.async.commit_group;" ::: "memory")
#define CP_WAIT1()  asm volatile("cp.async.wait_group 1;" ::: "memory")
#define CP_WAIT0()  asm volatile("cp.async.wait_group 0;" ::: "memory")
#define LDSM_X4(r, addr) \
    asm volatile("ldmatrix.sync.aligned.m8n8.x4.shared.b16 {%0,%1,%2,%3}, [%4];" \
        : "=r"((r)[0]), "=r"((r)[1]), "=r"((r)[2]), "=r"((r)[3]) : "r"(addr))
#define MMA16816(d, a, b0, b1) \
    asm volatile("mma.sync.aligned.m16n8k16.row.col.f32.bf16.bf16.f32 " \
        "{%0,%1,%2,%3}, {%4,%5,%6,%7}, {%8,%9}, {%0,%1,%2,%3};" \
        : "+f"((d)[0]), "+f"((d)[1]), "+f"((d)[2]), "+f"((d)[3]) \
        : "r"((a)[0]), "r"((a)[1]), "r"((a)[2]), "r"((a)[3]), "r"(b0), "r"(b1))

// ================= K1: per-channel partial sums (32-way, shuffle reduce) =====
__global__ void __launch_bounds__(128) k_stats(const float* __restrict__ x) {
    int c = blockIdx.x;
    int b = blockIdx.y;
    int tid = threadIdx.x;
    const float4* p = (const float4*)(x + ((size_t)(b * C_ + c)) * (H_ * W_));
    float sm = 0.f, ss = 0.f;
#pragma unroll
    for (int i = tid; i < (H_ * W_) / 4; i += 128) {
        float4 v = p[i];
        sm += (v.x + v.y) + (v.z + v.w);
        ss += fmaf(v.x, v.x, v.y * v.y) + fmaf(v.z, v.z, v.w * v.w);
    }
#pragma unroll
    for (int off = 16; off > 0; off >>= 1) {
        sm += __shfl_down_sync(0xFFFFFFFFu, sm, off);
        ss += __shfl_down_sync(0xFFFFFFFFu, ss, off);
    }
    __shared__ float a1[4], a2[4];
    if ((tid & 31) == 0) { a1[tid >> 5] = sm; a2[tid >> 5] = ss; }
    __syncthreads();
    if (tid == 0) {
        g_psum[b][c] = (a1[0] + a1[1]) + (a1[2] + a1[3]);
        g_pss[b][c]  = (a2[0] + a2[1]) + (a2[2] + a2[3]);
    }
}

// ================= K1b: finalize stats + thresholds (tiny) =================
__global__ void k_finalize(const float* __restrict__ g1, const float* __restrict__ b1,
                           const float* __restrict__ g2, const float* __restrict__ b2) {
    int i = threadIdx.x + blockIdx.x * blockDim.x;
    if (i >= 2 * C_) return;
    int br = i / C_, c = i % C_;
    float s = 0.f, q = 0.f;
#pragma unroll
    for (int k = 0; k < 32; k++) { s += g_psum[k][c]; q += g_pss[k][c]; }
    const float invn = 1.f / (float)(B_ * H_ * W_);
    float mu = s * invn;
    float var = q * invn - mu * mu;
    float rstd = rsqrtf(var + 1e-5f);
    float gamma = br ? g2[c] : g1[c];
    float beta  = br ? b2[c] : b1[c];
    float sc = gamma * rstd;
    g_scale[br][c] = sc;
    g_shift[br][c] = beta - sc * mu;
}

// ================= K2: pack weights to bf16 +-1, [br][tap][oc][ic] =========
__global__ void k_wpack(const float* __restrict__ w1, const float* __restrict__ w2) {
    int i = blockIdx.x * 256 + threadIdx.x;
    if (i >= 2 * 9 * C_ * (C_ / 2)) return;
    int cw = i % (C_ / 2);
    int t = i / (C_ / 2);
    int oc = t % C_; t /= C_;
    int tap = t % 9;
    int br = t / 9;
    int ky = tap / 3, kx = tap % 3;
    const float* w = br ? w2 : w1;
    int c0 = 2 * cw;
    float v0 = w[((oc * C_ + c0) * 3 + ky) * 3 + kx];
    float v1 = w[((oc * C_ + c0 + 1) * 3 + ky) * 3 + kx];
    unsigned lo = v0 > 0.f ? 0x3F80u : 0xBF80u;
    unsigned hi = v1 > 0.f ? 0x3F80u : 0xBF80u;
    g_wbf[i] = lo | (hi << 16);
}

// ========== K3: binarize (interleaved bit layout) + avgpool shortcut ==========
__global__ void __launch_bounds__(256) k_pack(const float* __restrict__ x) {
    __shared__ float s_scale[2 * C_], s_shift[2 * C_];
    int tid = threadIdx.x;
    for (int i = tid; i < 2 * C_; i += 256) {
        s_scale[i] = ((const float*)g_scale)[i];
        s_shift[i] = ((const float*)g_shift)[i];
    }
    __syncthreads();

    int gw = blockIdx.x * 8 + (tid >> 5);
    int lane = tid & 31;                 // = j (half-x index)
    int b = gw / (OH_ * 6);
    int rem = gw % (OH_ * 6);
    int oy = rem / 6;
    int wp = rem % 6;                    // 32-channel plane
    int c0 = wp * 32;

    const float* px = x + ((size_t)(b * C_ + c0)) * (H_ * W_) + (2 * oy) * W_ + 2 * lane;
    float* psc = &g_sc[b][c0][oy][lane];
    int y0 = 2 * oy;

    unsigned acc[8];                     // br*4 + (dy*2+dx)
#pragma unroll
    for (int k = 0; k < 8; k++) acc[k] = 0;

#pragma unroll 8
    for (int j = 0; j < 32; j++) {
        int c = c0 + j;
        const float* pc = px + (size_t)j * (H_ * W_);
        float2 r0 = *(const float2*)pc;
        float2 r1 = *(const float2*)(pc + W_);
        psc[(size_t)j * (OH_ * OW_)] = (r0.x + r0.y + r1.x + r1.y) * 0.25f;
        float s0 = s_scale[c],      t0 = s_shift[c];
        float s1 = s_scale[C_ + c], t1 = s_shift[C_ + c];
        unsigned bit = 1u << j;
        if (fmaf(s0, r0.x, t0) > 0.f) acc[0] |= bit;
        if (fmaf(s0, r0.y, t0) > 0.f) acc[1] |= bit;
        if (fmaf(s0, r1.x, t0) > 0.f) acc[2] |= bit;
        if (fmaf(s0, r1.y, t0) > 0.f) acc[3] |= bit;
        if (fmaf(s1, r0.x, t1) > 0.f) acc[4] |= bit;
        if (fmaf(s1, r0.y, t1) > 0.f) acc[5] |= bit;
        if (fmaf(s1, r1.x, t1) > 0.f) acc[6] |= bit;
        if (fmaf(s1, r1.y, t1) > 0.f) acc[7] |= bit;
    }

    // coalesced: lane j writes uint2 at word 2j of the [br][wp][b][y] row
#pragma unroll
    for (int br = 0; br < 2; br++)
#pragma unroll
        for (int dy = 0; dy < 2; dy++) {
            uint2 v = make_uint2(acc[br * 4 + 2 * dy], acc[br * 4 + 2 * dy + 1]);
            *(uint2*)&g_abits[br][wp][b][y0 + dy][2 * lane] = v;
        }
}

// ================= K4: bf16 HMMA conv, 4 CTAs/SM, half-K chunk pipeline =====
// CTA: 256 threads = 8 warps (4M x 2N). M=64 pixels (2 oy x 32 ox), N=96 oc.
// Warp tile 16x48. A fragments in registers (IMAD bit-spread).
// B streamed per (tap, half-K chunk): 18 chunks of 96x192B, double-buffered.
#define BCH_ST    208              // chunk row stride
#define BCH_B     19968            // 96*208
#define PAT_B     7680             // 6*5*256
#define PAT_OFF   (2 * BCH_B)
#define CONV_SMEM (PAT_OFF + PAT_B)   // 47616

__global__ void __launch_bounds__(256, 4) k_conv(const float* __restrict__ bias1,
                                                 const float* __restrict__ bias2,
                                                 float* __restrict__ out) {
    extern __shared__ __align__(16) char smem[];
    __shared__ float s_bias[96];
    uint32_t sb = smem_to_u32(smem);
    const uint32_t sbPAT = sb + PAT_OFF;

    int tid = threadIdx.x;
    int lane = tid & 31, w = tid >> 5;
    int wm = w & 3, wn = w >> 2;            // 4M x 2N warp grid
    int g = lane >> 2;                      // fragment row group 0..7
    int t2 = (lane & 3) * 2;                // fragment col pair base
    int yg = blockIdx.x;                    // 0..15 (2 oy rows each)
    int nh = blockIdx.y & 1, br = blockIdx.y >> 1;
    int b = blockIdx.z;
    int oy0 = yg * 2;
    int ocb = nh * 96;

    const float* bias = br ? bias2 : bias1;
    if (tid < 96) s_bias[tid] = bias[ocb + tid];

    const int8_t* gw8 = (const int8_t*)g_wbf + ((size_t)br * 9 * C_ + ocb) * 384;

    // ---- prologue: patch + chunk0 (group0), chunk1 (group1) ----
    {
        for (int i = tid; i < 480; i += 256) {
            int wd = i / 80;
            int r = i - wd * 80;
            int ylocal = r / 16;
            int t = r - ylocal * 16;
            int y = 2 * oy0 - 1 + ylocal;
            bool ok = (y >= 0);
            const unsigned* base = &g_abits[br][wd][b][ok ? y : 0][0];
            CP_ASYNC16(sbPAT + (uint32_t)((wd * 5 + ylocal) * 256 + t * 16),
                       (const int8_t*)base + t * 16, ok ? 16u : 0u);
        }
        for (int i = tid; i < 1152; i += 256) {        // tap0 chunk0
            int oc = i / 12, t = i - oc * 12;
            CP_ASYNC16(sb + (uint32_t)(oc * BCH_ST + t * 16),
                       gw8 + (size_t)oc * 384 + t * 16, 16u);
        }
        CP_COMMIT();                                    // G0
        for (int i = tid; i < 1152; i += 256) {        // tap0 chunk1
            int oc = i / 12, t = i - oc * 12;
            CP_ASYNC16(sb + BCH_B + (uint32_t)(oc * BCH_ST + t * 16),
                       gw8 + (size_t)oc * 384 + 192 + t * 16, 16u);
        }
        CP_COMMIT();                                    // G1
        CP_WAIT1();                                     // patch (G0) resident
        __syncthreads();
    }

    // ---- B ldmatrix fragment geometry (chunk stride 208) ----
    uint32_t boff[3];
    {
        int sub = lane & 7, gg = lane >> 3;
#pragma unroll
        for (int np = 0; np < 3; np++) {
            int row = wn * 48 + np * 16 + sub + ((gg >> 1) << 3);
            int kcol = (gg & 1) * 8;
            boff[np] = (uint32_t)(row * BCH_ST + kcol * 2);
        }
    }

    float d[6][4];
#pragma unroll
    for (int nt = 0; nt < 6; nt++)
#pragma unroll
        for (int e = 0; e < 4; e++) d[nt][e] = 0.f;

    int r_oy = wm >> 1;                      // local oy row 0..1
    int oxbase = (wm & 1) * 16 + g;          // + 8*i gives ox

    for (int it = 0; it < 18; it++) {
        int tap = it >> 1, ch = it & 1;
        int ky = tap / 3, kx = tap - 3 * (tap / 3);

        // ---- gather bit words (patch is prologue-stable; overlaps the wait) ----
        int yl = 2 * r_oy + ky;              // patch local row 0..4
        bool yok = !(oy0 == 0 && yl == 0);
        int par = (kx != 1) ? 1 : 0;
        uint32_t rb[2][3];
        uint32_t basew[2];
#pragma unroll
        for (int i = 0; i < 2; i++) {
            int ox = oxbase + 8 * i;
            bool ok = yok && !(kx == 0 && ox == 0);
            int j = ox - (kx == 0);
            int jc = j < 0 ? 0 : j;
            uint32_t addr = sbPAT + (uint32_t)(yl * 256 + (jc * 2 + par) * 4)
                          + (uint32_t)(3 * ch) * 1280u;
#pragma unroll
            for (int wdl = 0; wdl < 3; wdl++) {
                uint32_t v;
                asm volatile("ld.shared.b32 %0, [%1];" : "=r"(v) : "r"(addr + wdl * 1280));
                rb[i][wdl] = ok ? v : 0u;
            }
            basew[i] = ok ? 0xBF80BF80u : 0u;
        }

        // ---- wait: chunk(it) landed (chunk(it+1) may be in flight) ----
        if (it < 17) { CP_WAIT1(); } else { CP_WAIT0(); }
        __syncthreads();

        // ---- MMA over this chunk's 6 k-steps ----
        uint32_t bbase = sb + (uint32_t)(it & 1) * BCH_B;
#pragma unroll
        for (int kcl = 0; kcl < 6; kcl++) {
            uint32_t bf[3][4];
#pragma unroll
            for (int np = 0; np < 3; np++) LDSM_X4(bf[np], bbase + boff[np] + kcl * 32);
            int wdl = kcl >> 1;
            uint32_t sh2 = (uint32_t)(((kcl & 1) << 4) + t2);
            uint32_t af[4];
            {
                uint32_t m0 = (rb[0][wdl] >> sh2) & 0x303u;
                uint32_t m1 = (rb[1][wdl] >> sh2) & 0x303u;
                af[0] = ((m0 * 0x40008000u) & 0x80008000u) ^ basew[0];
                af[1] = ((m1 * 0x40008000u) & 0x80008000u) ^ basew[1];
                af[2] = (((m0 >> 8) * 0x40008000u) & 0x80008000u) ^ basew[0];
                af[3] = (((m1 >> 8) * 0x40008000u) & 0x80008000u) ^ basew[1];
            }
#pragma unroll
            for (int nt = 0; nt < 6; nt++) {
                int np = nt >> 1;
                if (nt & 1) { MMA16816(d[nt], af, bf[np][2], bf[np][3]); }
                else        { MMA16816(d[nt], af, bf[np][0], bf[np][1]); }
            }
        }

        __syncthreads();   // all warps done reading chunk(it) before its buffer reuse

        // ---- issue chunk(it+2) into the buffer just freed ----
        if (it < 16) {
            int tap2 = (it + 2) >> 1, ch2 = (it + 2) & 1;
            const int8_t* gwn = gw8 + (size_t)tap2 * C_ * 384 + ch2 * 192;
            uint32_t dstB = sb + (uint32_t)(it & 1) * BCH_B;
            for (int i = tid; i < 1152; i += 256) {
                int oc = i / 12, t = i - oc * 12;
                CP_ASYNC16(dstB + (uint32_t)(oc * BCH_ST + t * 16),
                           gwn + (size_t)oc * 384 + t * 16, 16u);
            }
            CP_COMMIT();
        }
    }

    // ---- epilogue: transpose via smem, fuse bias+relu+shortcut, coalesced out ----
    float* S = (float*)smem;     // S[c][m], c 0..95, m 0..63, stride 68 floats
    __syncthreads();
#pragma unroll
    for (int nt = 0; nt < 6; nt++)
#pragma unroll
        for (int e = 0; e < 4; e++) {
            int m = wm * 16 + (lane >> 2) + ((e >> 1) << 3);
            int c = wn * 48 + nt * 8 + ((lane & 3) << 1) + (e & 1);
            S[c * 68 + m] = d[nt][e];
        }
    __syncthreads();

    size_t ob = ((size_t)b * (2 * C_) + (size_t)br * C_ + ocb) * (OH_ * OW_) + (size_t)yg * 64;
    const float* scp = &g_sc[b][ocb][0][0] + yg * 64;
#pragma unroll
    for (int i = tid; i < 6144; i += 256) {
        int c = i >> 6, m = i & 63;
        float v = S[c * 68 + m] + s_bias[c];
        v = fmaxf(v, 0.f) + scp[(size_t)c * (OH_ * OW_) + m];
        out[ob + (size_t)c * (OH_ * OW_) + m] = v;
    }
}

// ================= launch =================
extern "C" void kernel_launch(void* const* d_in, const int* in_sizes, int n_in,
                              void* d_out, int out_size) {
    const float* x     = (const float*)d_in[0];
    const float* g1    = (const float*)d_in[1];
    const float* b1    = (const float*)d_in[2];
    const float* w1    = (const float*)d_in[3];
    const float* bias1 = (const float*)d_in[4];
    const float* g2    = (const float*)d_in[5];
    const float* b2    = (const float*)d_in[6];
    const float* w2    = (const float*)d_in[7];
    const float* bias2 = (const float*)d_in[8];
    float* out = (float*)d_out;

    cudaFuncSetAttribute(k_conv, cudaFuncAttributeMaxDynamicSharedMemorySize, CONV_SMEM);

    k_stats<<<dim3(C_, 32), 128>>>(x);
    k_wpack<<<(2 * 9 * C_ * (C_ / 2) + 255) / 256, 256>>>(w1, w2);
    k_finalize<<<2, C_>>>(g1, b1, g2, b2);
    k_pack<<<(B_ * OH_ * 6) / 8, 256>>>(x);
    dim3 gconv(16, 4, B_);
    k_conv<<<gconv, 256, CONV_SMEM>>>(bias1, bias2, out);
}

// round 15
// speedup vs baseline: 1.3781x; 1.0336x over previous
#include <cuda_runtime.h>
#include <cstdint>

// Problem constants
#define B_   32
#define C_   192
#define H_   64
#define W_   64
#define OH_  32
#define OW_  32

// -------- device scratch (no mallocs allowed) --------
__device__ float g_psum[32][C_];
__device__ float g_pss[32][C_];
__device__ float g_scale[2][C_];
__device__ float g_shift[2][C_];
__device__ unsigned g_wbf[2 * 9 * C_ * (C_ / 2)];         // bf16x2 weights [br][tap][oc][ic/2]
__device__ unsigned g_abits[2][6][B_][H_][64];            // bits [br][plane][b][y][j*2+par]
__device__ float    g_sc[B_][C_][OH_][OW_];               // shared avgpool shortcut

// ---------------- PTX helpers (sm_80-compatible) ----------------
__device__ __forceinline__ uint32_t smem_to_u32(const void* p) {
    uint32_t a;
    asm("{ .reg .u64 t; cvta.to.shared.u64 t, %1; cvt.u32.u64 %0, t; }" : "=r"(a) : "l"(p));
    return a;
}
#define CP_ASYNC16(dst, src, sz) \
    asm volatile("cp.async.cg.shared.global [%0], [%1], 16, %2;" \
        :: "r"(dst), "l"(src), "r"(sz) : "memory")
#define CP_COMMIT() asm volatile("cp.async.commit_group;" ::: "memory")
#define CP_WAIT1()  asm volatile("cp.async.wait_group 1;" ::: "memory")
#define CP_WAIT0()  asm volatile("cp.async.wait_group 0;" ::: "memory")
#define LDSM_X4(r, addr) \
    asm volatile("ldmatrix.sync.aligned.m8n8.x4.shared.b16 {%0,%1,%2,%3}, [%4];" \
        : "=r"((r)[0]), "=r"((r)[1]), "=r"((r)[2]), "=r"((r)[3]) : "r"(addr))
#define MMA16816(d, a, b0, b1) \
    asm volatile("mma.sync.aligned.m16n8k16.row.col.f32.bf16.bf16.f32 " \
        "{%0,%1,%2,%3}, {%4,%5,%6,%7}, {%8,%9}, {%0,%1,%2,%3};" \
        : "+f"((d)[0]), "+f"((d)[1]), "+f"((d)[2]), "+f"((d)[3]) \
        : "r"((a)[0]), "r"((a)[1]), "r"((a)[2]), "r"((a)[3]), "r"(b0), "r"(b1))

// ================= K1: per-channel partial sums (32-way, shuffle reduce) =====
__global__ void __launch_bounds__(128) k_stats(const float* __restrict__ x) {
    int c = blockIdx.x;
    int b = blockIdx.y;
    int tid = threadIdx.x;
    const float4* p = (const float4*)(x + ((size_t)(b * C_ + c)) * (H_ * W_));
    float sm = 0.f, ss = 0.f;
#pragma unroll
    for (int i = tid; i < (H_ * W_) / 4; i += 128) {
        float4 v = p[i];
        sm += (v.x + v.y) + (v.z + v.w);
        ss += fmaf(v.x, v.x, v.y * v.y) + fmaf(v.z, v.z, v.w * v.w);
    }
#pragma unroll
    for (int off = 16; off > 0; off >>= 1) {
        sm += __shfl_down_sync(0xFFFFFFFFu, sm, off);
        ss += __shfl_down_sync(0xFFFFFFFFu, ss, off);
    }
    __shared__ float a1[4], a2[4];
    if ((tid & 31) == 0) { a1[tid >> 5] = sm; a2[tid >> 5] = ss; }
    __syncthreads();
    if (tid == 0) {
        g_psum[b][c] = (a1[0] + a1[1]) + (a1[2] + a1[3]);
        g_pss[b][c]  = (a2[0] + a2[1]) + (a2[2] + a2[3]);
    }
}

// ======== K2: pack weights to bf16 +-1 AND finalize stats (merged) ========
__global__ void k_wpack(const float* __restrict__ w1, const float* __restrict__ w2,
                        const float* __restrict__ g1, const float* __restrict__ b1,
                        const float* __restrict__ g2, const float* __restrict__ b2) {
    int i = blockIdx.x * 256 + threadIdx.x;
    // finalize path (first 384 global threads; independent of wpack outputs)
    if (i < 2 * C_) {
        int br = i / C_, c = i % C_;
        float s = 0.f, q = 0.f;
#pragma unroll
        for (int k = 0; k < 32; k++) { s += g_psum[k][c]; q += g_pss[k][c]; }
        const float invn = 1.f / (float)(B_ * H_ * W_);
        float mu = s * invn;
        float var = q * invn - mu * mu;
        float rstd = rsqrtf(var + 1e-5f);
        float gamma = br ? g2[c] : g1[c];
        float beta  = br ? b2[c] : b1[c];
        float sc = gamma * rstd;
        g_scale[br][c] = sc;
        g_shift[br][c] = beta - sc * mu;
    }
    if (i >= 2 * 9 * C_ * (C_ / 2)) return;
    int cw = i % (C_ / 2);
    int t = i / (C_ / 2);
    int oc = t % C_; t /= C_;
    int tap = t % 9;
    int br = t / 9;
    int ky = tap / 3, kx = tap % 3;
    const float* w = br ? w2 : w1;
    int c0 = 2 * cw;
    float v0 = w[((oc * C_ + c0) * 3 + ky) * 3 + kx];
    float v1 = w[((oc * C_ + c0 + 1) * 3 + ky) * 3 + kx];
    unsigned lo = v0 > 0.f ? 0x3F80u : 0xBF80u;
    unsigned hi = v1 > 0.f ? 0x3F80u : 0xBF80u;
    g_wbf[i] = lo | (hi << 16);
}

// ========== K3: binarize (interleaved bit layout) + avgpool shortcut ==========
// Streaming (.cs) stores keep x resident in L2 (x was just read by k_stats).
__global__ void __launch_bounds__(256) k_pack(const float* __restrict__ x) {
    __shared__ float s_scale[2 * C_], s_shift[2 * C_];
    int tid = threadIdx.x;
    for (int i = tid; i < 2 * C_; i += 256) {
        s_scale[i] = ((const float*)g_scale)[i];
        s_shift[i] = ((const float*)g_shift)[i];
    }
    __syncthreads();

    int gw = blockIdx.x * 8 + (tid >> 5);
    int lane = tid & 31;                 // = j (half-x index)
    int b = gw / (OH_ * 6);
    int rem = gw % (OH_ * 6);
    int oy = rem / 6;
    int wp = rem % 6;                    // 32-channel plane
    int c0 = wp * 32;

    const float* px = x + ((size_t)(b * C_ + c0)) * (H_ * W_) + (2 * oy) * W_ + 2 * lane;
    float* psc = &g_sc[b][c0][oy][lane];
    int y0 = 2 * oy;

    unsigned acc[8];                     // br*4 + (dy*2+dx)
#pragma unroll
    for (int k = 0; k < 8; k++) acc[k] = 0;

#pragma unroll 8
    for (int j = 0; j < 32; j++) {
        int c = c0 + j;
        const float* pc = px + (size_t)j * (H_ * W_);
        float2 r0 = *(const float2*)pc;
        float2 r1 = *(const float2*)(pc + W_);
        __stcs(&psc[(size_t)j * (OH_ * OW_)], (r0.x + r0.y + r1.x + r1.y) * 0.25f);
        float s0 = s_scale[c],      t0 = s_shift[c];
        float s1 = s_scale[C_ + c], t1 = s_shift[C_ + c];
        unsigned bit = 1u << j;
        if (fmaf(s0, r0.x, t0) > 0.f) acc[0] |= bit;
        if (fmaf(s0, r0.y, t0) > 0.f) acc[1] |= bit;
        if (fmaf(s0, r1.x, t0) > 0.f) acc[2] |= bit;
        if (fmaf(s0, r1.y, t0) > 0.f) acc[3] |= bit;
        if (fmaf(s1, r0.x, t1) > 0.f) acc[4] |= bit;
        if (fmaf(s1, r0.y, t1) > 0.f) acc[5] |= bit;
        if (fmaf(s1, r1.x, t1) > 0.f) acc[6] |= bit;
        if (fmaf(s1, r1.y, t1) > 0.f) acc[7] |= bit;
    }

    // coalesced streaming store: lane j writes uint2 at word 2j of the row
#pragma unroll
    for (int br = 0; br < 2; br++)
#pragma unroll
        for (int dy = 0; dy < 2; dy++) {
            unsigned long long v = (unsigned long long)acc[br * 4 + 2 * dy]
                                 | ((unsigned long long)acc[br * 4 + 2 * dy + 1] << 32);
            __stcs((unsigned long long*)&g_abits[br][wp][b][y0 + dy][2 * lane], v);
        }
}

// ================= K4: bf16 HMMA conv, 4 CTAs/SM, half-K chunk pipeline =====
// CTA: 256 threads = 8 warps (4M x 2N). M=64 pixels (2 oy x 32 ox), N=96 oc.
// Warp tile 16x48. A fragments in registers (IMAD bit-spread).
// B streamed per (tap, half-K chunk): 18 chunks of 96x192B, double-buffered.
#define BCH_ST    208              // chunk row stride
#define BCH_B     19968            // 96*208
#define PAT_B     7680             // 6*5*256
#define PAT_OFF   (2 * BCH_B)
#define CONV_SMEM (PAT_OFF + PAT_B)   // 47616

__global__ void __launch_bounds__(256, 4) k_conv(const float* __restrict__ bias1,
                                                 const float* __restrict__ bias2,
                                                 float* __restrict__ out) {
    extern __shared__ __align__(16) char smem[];
    __shared__ float s_bias[96];
    uint32_t sb = smem_to_u32(smem);
    const uint32_t sbPAT = sb + PAT_OFF;

    int tid = threadIdx.x;
    int lane = tid & 31, w = tid >> 5;
    int wm = w & 3, wn = w >> 2;            // 4M x 2N warp grid
    int g = lane >> 2;                      // fragment row group 0..7
    int t2 = (lane & 3) * 2;                // fragment col pair base
    int yg = blockIdx.x;                    // 0..15 (2 oy rows each)
    int nh = blockIdx.y & 1, br = blockIdx.y >> 1;
    int b = blockIdx.z;
    int oy0 = yg * 2;
    int ocb = nh * 96;

    const float* bias = br ? bias2 : bias1;
    if (tid < 96) s_bias[tid] = bias[ocb + tid];

    const int8_t* gw8 = (const int8_t*)g_wbf + ((size_t)br * 9 * C_ + ocb) * 384;

    // ---- prologue: patch + chunk0 (group0), chunk1 (group1) ----
    {
        for (int i = tid; i < 480; i += 256) {
            int wd = i / 80;
            int r = i - wd * 80;
            int ylocal = r / 16;
            int t = r - ylocal * 16;
            int y = 2 * oy0 - 1 + ylocal;
            bool ok = (y >= 0);
            const unsigned* base = &g_abits[br][wd][b][ok ? y : 0][0];
            CP_ASYNC16(sbPAT + (uint32_t)((wd * 5 + ylocal) * 256 + t * 16),
                       (const int8_t*)base + t * 16, ok ? 16u : 0u);
        }
        for (int i = tid; i < 1152; i += 256) {        // tap0 chunk0
            int oc = i / 12, t = i - oc * 12;
            CP_ASYNC16(sb + (uint32_t)(oc * BCH_ST + t * 16),
                       gw8 + (size_t)oc * 384 + t * 16, 16u);
        }
        CP_COMMIT();                                    // G0
        for (int i = tid; i < 1152; i += 256) {        // tap0 chunk1
            int oc = i / 12, t = i - oc * 12;
            CP_ASYNC16(sb + BCH_B + (uint32_t)(oc * BCH_ST + t * 16),
                       gw8 + (size_t)oc * 384 + 192 + t * 16, 16u);
        }
        CP_COMMIT();                                    // G1
        CP_WAIT1();                                     // patch (G0) resident
        __syncthreads();
    }

    // ---- B ldmatrix fragment geometry (chunk stride 208) ----
    uint32_t boff[3];
    {
        int sub = lane & 7, gg = lane >> 3;
#pragma unroll
        for (int np = 0; np < 3; np++) {
            int row = wn * 48 + np * 16 + sub + ((gg >> 1) << 3);
            int kcol = (gg & 1) * 8;
            boff[np] = (uint32_t)(row * BCH_ST + kcol * 2);
        }
    }

    float d[6][4];
#pragma unroll
    for (int nt = 0; nt < 6; nt++)
#pragma unroll
        for (int e = 0; e < 4; e++) d[nt][e] = 0.f;

    int r_oy = wm >> 1;                      // local oy row 0..1
    int oxbase = (wm & 1) * 16 + g;          // + 8*i gives ox

    for (int it = 0; it < 18; it++) {
        int tap = it >> 1, ch = it & 1;
        int ky = tap / 3, kx = tap - 3 * (tap / 3);

        // ---- gather bit words (patch is prologue-stable; overlaps the wait) ----
        int yl = 2 * r_oy + ky;              // patch local row 0..4
        bool yok = !(oy0 == 0 && yl == 0);
        int par = (kx != 1) ? 1 : 0;
        uint32_t rb[2][3];
        uint32_t basew[2];
#pragma unroll
        for (int i = 0; i < 2; i++) {
            int ox = oxbase + 8 * i;
            bool ok = yok && !(kx == 0 && ox == 0);
            int j = ox - (kx == 0);
            int jc = j < 0 ? 0 : j;
            uint32_t addr = sbPAT + (uint32_t)(yl * 256 + (jc * 2 + par) * 4)
                          + (uint32_t)(3 * ch) * 1280u;
#pragma unroll
            for (int wdl = 0; wdl < 3; wdl++) {
                uint32_t v;
                asm volatile("ld.shared.b32 %0, [%1];" : "=r"(v) : "r"(addr + wdl * 1280));
                rb[i][wdl] = ok ? v : 0u;
            }
            basew[i] = ok ? 0xBF80BF80u : 0u;
        }

        // ---- wait: chunk(it) landed (chunk(it+1) may be in flight) ----
        if (it < 17) { CP_WAIT1(); } else { CP_WAIT0(); }
        __syncthreads();

        // ---- MMA over this chunk's 6 k-steps ----
        uint32_t bbase = sb + (uint32_t)(it & 1) * BCH_B;
#pragma unroll
        for (int kcl = 0; kcl < 6; kcl++) {
            uint32_t bf[3][4];
#pragma unroll
            for (int np = 0; np < 3; np++) LDSM_X4(bf[np], bbase + boff[np] + kcl * 32);
            int wdl = kcl >> 1;
            uint32_t sh2 = (uint32_t)(((kcl & 1) << 4) + t2);
            uint32_t af[4];
            {
                uint32_t m0 = (rb[0][wdl] >> sh2) & 0x303u;
                uint32_t m1 = (rb[1][wdl] >> sh2) & 0x303u;
                af[0] = ((m0 * 0x40008000u) & 0x80008000u) ^ basew[0];
                af[1] = ((m1 * 0x40008000u) & 0x80008000u) ^ basew[1];
                af[2] = (((m0 >> 8) * 0x40008000u) & 0x80008000u) ^ basew[0];
                af[3] = (((m1 >> 8) * 0x40008000u) & 0x80008000u) ^ basew[1];
            }
#pragma unroll
            for (int nt = 0; nt < 6; nt++) {
                int np = nt >> 1;
                if (nt & 1) { MMA16816(d[nt], af, bf[np][2], bf[np][3]); }
                else        { MMA16816(d[nt], af, bf[np][0], bf[np][1]); }
            }
        }

        __syncthreads();   // all warps done reading chunk(it) before its buffer reuse

        // ---- issue chunk(it+2) into the buffer just freed ----
        if (it < 16) {
            int tap2 = (it + 2) >> 1, ch2 = (it + 2) & 1;
            const int8_t* gwn = gw8 + (size_t)tap2 * C_ * 384 + ch2 * 192;
            uint32_t dstB = sb + (uint32_t)(it & 1) * BCH_B;
            for (int i = tid; i < 1152; i += 256) {
                int oc = i / 12, t = i - oc * 12;
                CP_ASYNC16(dstB + (uint32_t)(oc * BCH_ST + t * 16),
                           gwn + (size_t)oc * 384 + t * 16, 16u);
            }
            CP_COMMIT();
        }
    }

    // ---- epilogue: transpose via smem, fuse bias+relu+shortcut, coalesced out ----
    float* S = (float*)smem;     // S[c][m], c 0..95, m 0..63, stride 68 floats
    __syncthreads();
#pragma unroll
    for (int nt = 0; nt < 6; nt++)
#pragma unroll
        for (int e = 0; e < 4; e++) {
            int m = wm * 16 + (lane >> 2) + ((e >> 1) << 3);
            int c = wn * 48 + nt * 8 + ((lane & 3) << 1) + (e & 1);
            S[c * 68 + m] = d[nt][e];
        }
    __syncthreads();

    size_t ob = ((size_t)b * (2 * C_) + (size_t)br * C_ + ocb) * (OH_ * OW_) + (size_t)yg * 64;
    const float* scp = &g_sc[b][ocb][0][0] + yg * 64;
#pragma unroll
    for (int i = tid; i < 6144; i += 256) {
        int c = i >> 6, m = i & 63;
        float v = S[c * 68 + m] + s_bias[c];
        v = fmaxf(v, 0.f) + __ldcs(&scp[(size_t)c * (OH_ * OW_) + m]);
        __stcs(&out[ob + (size_t)c * (OH_ * OW_) + m], v);
    }
}

// ================= launch =================
extern "C" void kernel_launch(void* const* d_in, const int* in_sizes, int n_in,
                              void* d_out, int out_size) {
    const float* x     = (const float*)d_in[0];
    const float* g1    = (const float*)d_in[1];
    const float* b1    = (const float*)d_in[2];
    const float* w1    = (const float*)d_in[3];
    const float* bias1 = (const float*)d_in[4];
    const float* g2    = (const float*)d_in[5];
    const float* b2    = (const float*)d_in[6];
    const float* w2    = (const float*)d_in[7];
    const float* bias2 = (const float*)d_in[8];
    float* out = (float*)d_out;

    cudaFuncSetAttribute(k_conv, cudaFuncAttributeMaxDynamicSharedMemorySize, CONV_SMEM);

    k_stats<<<dim3(C_, 32), 128>>>(x);
    k_wpack<<<(2 * 9 * C_ * (C_ / 2) + 255) / 256, 256>>>(w1, w2, g1, b1, g2, b2);
    k_pack<<<(B_ * OH_ * 6) / 8, 256>>>(x);
    dim3 gconv(16, 4, B_);
    k_conv<<<gconv, 256, CONV_SMEM>>>(bias1, bias2, out);
}